// round 1
// baseline (speedup 1.0000x reference)
#include <cuda_runtime.h>

// FAST attention (p=2 Taylor linear attention), fp32 scalar baseline.
// B=2, H=16, N=4096, D=32. A0=1, A1=1, A2=0.5.
//
// Phase 1: per head reduce over n:
//   S3[f1*32+f2][e] = sum_n k[n,f1]*k[n,f2]*v_aug[n,e]   (v_aug col32 = 1 -> k2sum)
//   S2[d][e]        = sum_n k[n,d]*v_aug[n,e]            (col32 = ksum)
//   sv[e]           = sum_n v[n,e]
// Phase 2: per query n:
//   num[e] = sv[e] + q@S2[:,e] + 0.5*q2@S3[:,e]
//   den    = 4096 + q@S2[:,32] + 0.5*q2@S3[:,32]
//   out    = num/den

#define NB 2
#define NH 16
#define NSEQ 4096
#define DD 32
#define BH (NB * NH)
#define D2 1024
#define ES 36  // padded stride for 33 used columns (float4-aligned rows)

__device__ float g_S3[BH * D2 * ES];   // ~4.7 MB scratch
__device__ float g_S2[BH * DD * ES];   // cols 0..31 = K^T V, col 32 = ksum
__device__ float g_sv[BH * DD];

// ---------------------------------------------------------------- zero init
__global__ void zero_small_kernel() {
    int i = blockIdx.x * blockDim.x + threadIdx.x;
    if (i < BH * DD * ES) g_S2[i] = 0.0f;
    if (i < BH * DD)      g_sv[i] = 0.0f;
}

// ---------------------------------------------------------------- kernel A
// S2 (+ksum col) and sv via split-N partial sums + atomics.
// grid (BH, 8 chunks), 64 threads; thread owns 4x4 of the 32x32 output.
__global__ __launch_bounds__(64) void kernelA(const float* __restrict__ k,
                                              const float* __restrict__ v) {
    __shared__ float kt[32][ES];
    __shared__ float vt[32][ES];
    const int bh = blockIdx.x;
    const int chunk = blockIdx.y;
    const int tid = threadIdx.x;
    const int di = (tid >> 3) * 4;
    const int ej = (tid & 7) * 4;
    const float* kb = k + (size_t)bh * NSEQ * DD;
    const float* vb = v + (size_t)bh * NSEQ * DD;

    float s2[4][4] = {};
    float ks[4] = {};
    float sv4[4] = {};

    for (int tile = 0; tile < (NSEQ / 8) / 32; ++tile) {  // 16 tiles of 32 rows
        const int rowbase = chunk * (NSEQ / 8) + tile * 32;
#pragma unroll
        for (int j = 0; j < 4; ++j) {
            int idx = j * 64 + tid;            // 256 float4 per tensor
            int r = idx >> 3, c = (idx & 7) * 4;
            *(float4*)&kt[r][c] = *(const float4*)&kb[(size_t)(rowbase + r) * DD + c];
            *(float4*)&vt[r][c] = *(const float4*)&vb[(size_t)(rowbase + r) * DD + c];
        }
        __syncthreads();
#pragma unroll
        for (int t = 0; t < 32; ++t) {
            float4 kd = *(float4*)&kt[t][di];
            float4 ve = *(float4*)&vt[t][ej];
            s2[0][0] += kd.x * ve.x; s2[0][1] += kd.x * ve.y; s2[0][2] += kd.x * ve.z; s2[0][3] += kd.x * ve.w;
            s2[1][0] += kd.y * ve.x; s2[1][1] += kd.y * ve.y; s2[1][2] += kd.y * ve.z; s2[1][3] += kd.y * ve.w;
            s2[2][0] += kd.z * ve.x; s2[2][1] += kd.z * ve.y; s2[2][2] += kd.z * ve.z; s2[2][3] += kd.z * ve.w;
            s2[3][0] += kd.w * ve.x; s2[3][1] += kd.w * ve.y; s2[3][2] += kd.w * ve.z; s2[3][3] += kd.w * ve.w;
            if ((tid & 7) == 0) { ks[0] += kd.x; ks[1] += kd.y; ks[2] += kd.z; ks[3] += kd.w; }
            if (tid < 8)        { sv4[0] += ve.x; sv4[1] += ve.y; sv4[2] += ve.z; sv4[3] += ve.w; }
        }
        __syncthreads();
    }
#pragma unroll
    for (int a = 0; a < 4; ++a)
#pragma unroll
        for (int b = 0; b < 4; ++b)
            atomicAdd(&g_S2[(bh * DD + di + a) * ES + ej + b], s2[a][b]);
    if ((tid & 7) == 0)
#pragma unroll
        for (int a = 0; a < 4; ++a)
            atomicAdd(&g_S2[(bh * DD + di + a) * ES + 32], ks[a]);
    if (tid < 8)
#pragma unroll
        for (int b = 0; b < 4; ++b)
            atomicAdd(&g_sv[bh * DD + ej + b], sv4[b]);
}

// ---------------------------------------------------------------- kernel B
// S3[f1*32+f2][e] = sum_n k[n,f1]*k[n,f2]*v_aug[n,e].
// grid (BH, 8): block handles 4 f1 values. 256 threads = 4 f1-groups x
// (32 f2 x 2 e-halves of 16). Thread: 16 fp32 accumulators (+den col).
__global__ __launch_bounds__(256) void kernelB(const float* __restrict__ k,
                                               const float* __restrict__ v) {
    __shared__ float kt[32][ES];
    __shared__ float vt[32][ES];
    const int bh = blockIdx.x;
    const int f1 = blockIdx.y * 4 + (threadIdx.x >> 6);
    const int l = threadIdx.x & 63;
    const int f2 = l >> 1;
    const int e0 = (l & 1) * 16;
    const float* kb = k + (size_t)bh * NSEQ * DD;
    const float* vb = v + (size_t)bh * NSEQ * DD;

    float acc[16] = {};
    float acc32 = 0.0f;

    for (int tile = 0; tile < NSEQ / 32; ++tile) {
        const int rowbase = tile * 32;
        {
            int idx = threadIdx.x;             // exactly 256 float4 each
            int r = idx >> 3, c = (idx & 7) * 4;
            *(float4*)&kt[r][c] = *(const float4*)&kb[(size_t)(rowbase + r) * DD + c];
            *(float4*)&vt[r][c] = *(const float4*)&vb[(size_t)(rowbase + r) * DD + c];
        }
        __syncthreads();
#pragma unroll
        for (int t = 0; t < 32; ++t) {
            float p = kt[t][f1] * kt[t][f2];
            float4 v0 = *(float4*)&vt[t][e0];
            float4 v1 = *(float4*)&vt[t][e0 + 4];
            float4 v2 = *(float4*)&vt[t][e0 + 8];
            float4 v3 = *(float4*)&vt[t][e0 + 12];
            acc[0]  += p * v0.x; acc[1]  += p * v0.y; acc[2]  += p * v0.z; acc[3]  += p * v0.w;
            acc[4]  += p * v1.x; acc[5]  += p * v1.y; acc[6]  += p * v1.z; acc[7]  += p * v1.w;
            acc[8]  += p * v2.x; acc[9]  += p * v2.y; acc[10] += p * v2.z; acc[11] += p * v2.w;
            acc[12] += p * v3.x; acc[13] += p * v3.y; acc[14] += p * v3.z; acc[15] += p * v3.w;
            if (e0 == 0) acc32 += p;           // v_aug col 32 == 1
        }
        __syncthreads();
    }
    float* dst = &g_S3[((size_t)bh * D2 + f1 * 32 + f2) * ES];
#pragma unroll
    for (int x = 0; x < 16; ++x) dst[e0 + x] = acc[x];
    if (e0 == 0) dst[32] = acc32;
}

// ---------------------------------------------------------------- kernel C
// Phase 2. grid (BH, 64): block = 64 query rows x 4 e-groups (8 e each).
// q row lives in registers; S3 streamed through smem in 128-row chunks.
__global__ __launch_bounds__(256) void kernelC(const float* __restrict__ q,
                                               float* __restrict__ out) {
    __shared__ float qs[64][ES];
    __shared__ float s3s[128][ES];
    __shared__ float s2s[DD][ES];
    __shared__ float svs[DD];
    const int bh = blockIdx.x;
    const int rowbase = blockIdx.y * 64;
    const int tid = threadIdx.x;
    const int rl = tid >> 2;
    const int e0 = (tid & 3) * 8;
    const float* qb = q + (size_t)bh * NSEQ * DD;

    // load q tile (64x32), S2 block, sv
#pragma unroll
    for (int j = 0; j < 2; ++j) {
        int idx = j * 256 + tid;               // 512 float4
        int r = idx >> 3, c = (idx & 7) * 4;
        *(float4*)&qs[r][c] = *(const float4*)&qb[(size_t)(rowbase + r) * DD + c];
    }
    {
        const float4* s2g = (const float4*)&g_S2[bh * DD * ES];
        for (int idx = tid; idx < (DD * ES) / 4; idx += 256)
            ((float4*)s2s)[idx] = s2g[idx];
        if (tid < 8) ((float4*)svs)[tid] = ((const float4*)&g_sv[bh * DD])[tid];
    }
    __syncthreads();

    float qreg[32];
#pragma unroll
    for (int i = 0; i < 32; ++i) qreg[i] = qs[rl][i];

    float acc[8] = {};
    float den2 = 0.0f;

    for (int chunk = 0; chunk < 8; ++chunk) {
        const float4* src = (const float4*)&g_S3[((size_t)bh * D2 + chunk * 128) * ES];
        for (int idx = tid; idx < (128 * ES) / 4; idx += 256)
            ((float4*)s3s)[idx] = src[idx];
        __syncthreads();
        for (int i = 0; i < 4; ++i) {
            float w = qs[rl][chunk * 4 + i];   // q[f1], via smem (dynamic index)
            const float* s3row = &s3s[i * 32][0];
#pragma unroll
            for (int f2 = 0; f2 < 32; ++f2) {
                float a = w * qreg[f2];
                float4 sa = *(const float4*)&s3row[f2 * ES + e0];
                float4 sb = *(const float4*)&s3row[f2 * ES + e0 + 4];
                acc[0] += a * sa.x; acc[1] += a * sa.y; acc[2] += a * sa.z; acc[3] += a * sa.w;
                acc[4] += a * sb.x; acc[5] += a * sb.y; acc[6] += a * sb.z; acc[7] += a * sb.w;
                den2 += a * s3row[f2 * ES + 32];
            }
        }
        __syncthreads();
    }

    // small terms: q @ S2 (+ ksum col)
    float y2[8] = {};
    float den1 = 0.0f;
#pragma unroll
    for (int d = 0; d < 32; ++d) {
        float wq = qreg[d];
        float4 sa = *(const float4*)&s2s[d][e0];
        float4 sb = *(const float4*)&s2s[d][e0 + 4];
        y2[0] += wq * sa.x; y2[1] += wq * sa.y; y2[2] += wq * sa.z; y2[3] += wq * sa.w;
        y2[4] += wq * sb.x; y2[5] += wq * sb.y; y2[6] += wq * sb.z; y2[7] += wq * sb.w;
        den1 += wq * s2s[d][32];
    }

    const float den = 4096.0f + den1 + 0.5f * den2;   // A0*N + A1*.. + A2*..
    const float inv = 1.0f / den;
    const int row = rowbase + rl;
    float* ob = out + ((size_t)bh * NSEQ + row) * DD + e0;
#pragma unroll
    for (int x = 0; x < 8; ++x) {
        float num = svs[e0 + x] + y2[x] + 0.5f * acc[x];
        ob[x] = num * inv;
    }
}

// ---------------------------------------------------------------- launch
extern "C" void kernel_launch(void* const* d_in, const int* in_sizes, int n_in,
                              void* d_out, int out_size) {
    const float* q = (const float*)d_in[0];
    const float* k = (const float*)d_in[1];
    const float* v = (const float*)d_in[2];
    float* out = (float*)d_out;
    (void)in_sizes; (void)n_in; (void)out_size;

    zero_small_kernel<<<(BH * DD * ES + 255) / 256, 256>>>();
    kernelA<<<dim3(BH, 8), 64>>>(k, v);
    kernelB<<<dim3(BH, 8), 256>>>(k, v);
    kernelC<<<dim3(BH, 64), 256>>>(q, out);
}

// round 2
// speedup vs baseline: 2.4258x; 2.4258x over previous
#include <cuda_runtime.h>

// FAST attention (p=2 Taylor linear attention), fp32, symmetry-packed.
// B=2, H=16, N=4096, D=32. A0=1, A1=1, A2=0.5.
//
// S3 is symmetric in (f1,f2): store only 528 upper-triangle pair-rows,
// with off-diagonal factor 2 folded in (S3p). Phase 2 sums over pairs.
// v is augmented with a constant-1 column (col 32) so the denominator
// sums ride along as column 32 of S2/S3p.

#define NB 2
#define NH 16
#define NSEQ 4096
#define DD 32
#define BH (NB * NH)
#define NPAIR 528          // 32*33/2
#define NPAIR_PAD 544      // 17 warps * 32
#define ESS 36             // row stride for S2/S3p (float4-aligned)
#define ESQ 33             // q smem row stride (conflict-free lane access)

__device__ float g_S3p[BH * NPAIR_PAD * ESS];  // ~2.5 MB
__device__ float g_S2[BH * DD * ESS];          // cols 0..31 = K^T V, col 32 = ksum
__device__ float g_sv[BH * DD];

// ---------------------------------------------------------------- zero init
__global__ void zero_kernel() {
    int i = blockIdx.x * blockDim.x + threadIdx.x;
    if (i < BH * NPAIR_PAD * ESS) g_S3p[i] = 0.0f;
    if (i < BH * DD * ESS)        g_S2[i] = 0.0f;
    if (i < BH * DD)              g_sv[i] = 0.0f;
}

// ---------------------------------------------------------------- kernel A
// S2 (+ksum col) and sv via split-N partial sums + atomics. (unchanged)
__global__ __launch_bounds__(64) void kernelA(const float* __restrict__ k,
                                              const float* __restrict__ v) {
    __shared__ float kt[32][ESS];
    __shared__ float vt[32][ESS];
    const int bh = blockIdx.x;
    const int chunk = blockIdx.y;
    const int tid = threadIdx.x;
    const int di = (tid >> 3) * 4;
    const int ej = (tid & 7) * 4;
    const float* kb = k + (size_t)bh * NSEQ * DD;
    const float* vb = v + (size_t)bh * NSEQ * DD;

    float s2[4][4] = {};
    float ks[4] = {};
    float sv4[4] = {};

    for (int tile = 0; tile < (NSEQ / 8) / 32; ++tile) {
        const int rowbase = chunk * (NSEQ / 8) + tile * 32;
#pragma unroll
        for (int j = 0; j < 4; ++j) {
            int idx = j * 64 + tid;
            int r = idx >> 3, c = (idx & 7) * 4;
            *(float4*)&kt[r][c] = *(const float4*)&kb[(size_t)(rowbase + r) * DD + c];
            *(float4*)&vt[r][c] = *(const float4*)&vb[(size_t)(rowbase + r) * DD + c];
        }
        __syncthreads();
#pragma unroll
        for (int t = 0; t < 32; ++t) {
            float4 kd = *(float4*)&kt[t][di];
            float4 ve = *(float4*)&vt[t][ej];
            s2[0][0] += kd.x * ve.x; s2[0][1] += kd.x * ve.y; s2[0][2] += kd.x * ve.z; s2[0][3] += kd.x * ve.w;
            s2[1][0] += kd.y * ve.x; s2[1][1] += kd.y * ve.y; s2[1][2] += kd.y * ve.z; s2[1][3] += kd.y * ve.w;
            s2[2][0] += kd.z * ve.x; s2[2][1] += kd.z * ve.y; s2[2][2] += kd.z * ve.z; s2[2][3] += kd.z * ve.w;
            s2[3][0] += kd.w * ve.x; s2[3][1] += kd.w * ve.y; s2[3][2] += kd.w * ve.z; s2[3][3] += kd.w * ve.w;
            if ((tid & 7) == 0) { ks[0] += kd.x; ks[1] += kd.y; ks[2] += kd.z; ks[3] += kd.w; }
            if (tid < 8)        { sv4[0] += ve.x; sv4[1] += ve.y; sv4[2] += ve.z; sv4[3] += ve.w; }
        }
        __syncthreads();
    }
#pragma unroll
    for (int a = 0; a < 4; ++a)
#pragma unroll
        for (int b = 0; b < 4; ++b)
            atomicAdd(&g_S2[(bh * DD + di + a) * ESS + ej + b], s2[a][b]);
    if ((tid & 7) == 0)
#pragma unroll
        for (int a = 0; a < 4; ++a)
            atomicAdd(&g_S2[(bh * DD + di + a) * ESS + 32], ks[a]);
    if (tid < 8)
#pragma unroll
        for (int b = 0; b < 4; ++b)
            atomicAdd(&g_sv[bh * DD + ej + b], sv4[b]);
}

// ---------------------------------------------------------------- kernel B
// S3p[p][e] = w_p * sum_n k[n,f1]*k[n,f2]*v_aug[n,e], p over upper triangle,
// w_p = 2 for off-diagonal, 1 on diagonal. 1 warp = 32 pairs; lane owns all
// 33 columns (v row read is warp-broadcast). N split into 4 chunks, merged
// with atomicAdd.
__global__ __launch_bounds__(32) void kernelB(const float* __restrict__ k,
                                              const float* __restrict__ v) {
    __shared__ float kt[32 * ESS];
    __shared__ float vt[32 * ESS];
    const int bh = blockIdx.x;
    const int nch = blockIdx.y;
    const int p = blockIdx.z * 32 + threadIdx.x;
    const bool active = p < NPAIR;
    const int pp = active ? p : 0;

    // invert triangular index: pp -> (f1, f2), f2 >= f1
    int f1 = 0, off = 0;
    while (f1 < 31 && off + (32 - f1) <= pp) { off += 32 - f1; ++f1; }
    const int f2 = f1 + (pp - off);

    const float4* kb4 = (const float4*)(k + ((size_t)bh * NSEQ + nch * (NSEQ / 4)) * DD);
    const float4* vb4 = (const float4*)(v + ((size_t)bh * NSEQ + nch * (NSEQ / 4)) * DD);

    float4 c0 = {0,0,0,0}, c1 = {0,0,0,0}, c2 = {0,0,0,0}, c3 = {0,0,0,0};
    float4 c4 = {0,0,0,0}, c5 = {0,0,0,0}, c6 = {0,0,0,0}, c7 = {0,0,0,0};
    float den = 0.0f;

    for (int t = 0; t < (NSEQ / 4) / 32; ++t) {   // 8 tiles of 32 rows
#pragma unroll
        for (int j = 0; j < 8; ++j) {
            int idx = j * 32 + threadIdx.x;       // 256 float4 per tensor
            int r = idx >> 3, c = (idx & 7) * 4;
            *(float4*)&kt[r * ESS + c] = kb4[t * 256 + idx];
            *(float4*)&vt[r * ESS + c] = vb4[t * 256 + idx];
        }
        __syncwarp();
#pragma unroll 4
        for (int n = 0; n < 32; ++n) {
            const float a = kt[n * ESS + f1] * kt[n * ESS + f2];
            const float* vr = vt + n * ESS;
            float4 b;
            b = *(const float4*)(vr +  0); c0.x += a*b.x; c0.y += a*b.y; c0.z += a*b.z; c0.w += a*b.w;
            b = *(const float4*)(vr +  4); c1.x += a*b.x; c1.y += a*b.y; c1.z += a*b.z; c1.w += a*b.w;
            b = *(const float4*)(vr +  8); c2.x += a*b.x; c2.y += a*b.y; c2.z += a*b.z; c2.w += a*b.w;
            b = *(const float4*)(vr + 12); c3.x += a*b.x; c3.y += a*b.y; c3.z += a*b.z; c3.w += a*b.w;
            b = *(const float4*)(vr + 16); c4.x += a*b.x; c4.y += a*b.y; c4.z += a*b.z; c4.w += a*b.w;
            b = *(const float4*)(vr + 20); c5.x += a*b.x; c5.y += a*b.y; c5.z += a*b.z; c5.w += a*b.w;
            b = *(const float4*)(vr + 24); c6.x += a*b.x; c6.y += a*b.y; c6.z += a*b.z; c6.w += a*b.w;
            b = *(const float4*)(vr + 28); c7.x += a*b.x; c7.y += a*b.y; c7.z += a*b.z; c7.w += a*b.w;
            den += a;
        }
        __syncwarp();
    }

    if (active) {
        const float w = (f1 == f2) ? 1.0f : 2.0f;
        float* dst = g_S3p + ((size_t)bh * NPAIR_PAD + p) * ESS;
        atomicAdd(dst +  0, w*c0.x); atomicAdd(dst +  1, w*c0.y); atomicAdd(dst +  2, w*c0.z); atomicAdd(dst +  3, w*c0.w);
        atomicAdd(dst +  4, w*c1.x); atomicAdd(dst +  5, w*c1.y); atomicAdd(dst +  6, w*c1.z); atomicAdd(dst +  7, w*c1.w);
        atomicAdd(dst +  8, w*c2.x); atomicAdd(dst +  9, w*c2.y); atomicAdd(dst + 10, w*c2.z); atomicAdd(dst + 11, w*c2.w);
        atomicAdd(dst + 12, w*c3.x); atomicAdd(dst + 13, w*c3.y); atomicAdd(dst + 14, w*c3.z); atomicAdd(dst + 15, w*c3.w);
        atomicAdd(dst + 16, w*c4.x); atomicAdd(dst + 17, w*c4.y); atomicAdd(dst + 18, w*c4.z); atomicAdd(dst + 19, w*c4.w);
        atomicAdd(dst + 20, w*c5.x); atomicAdd(dst + 21, w*c5.y); atomicAdd(dst + 22, w*c5.z); atomicAdd(dst + 23, w*c5.w);
        atomicAdd(dst + 24, w*c6.x); atomicAdd(dst + 25, w*c6.y); atomicAdd(dst + 26, w*c6.z); atomicAdd(dst + 27, w*c6.w);
        atomicAdd(dst + 28, w*c7.x); atomicAdd(dst + 29, w*c7.y); atomicAdd(dst + 30, w*c7.z); atomicAdd(dst + 31, w*c7.w);
        atomicAdd(dst + 32, w*den);
    }
}

// ---------------------------------------------------------------- kernel C
// out[n,e] = (sv[e] + q@S2[:,e] + 0.5*sum_p q[f1]q[f2]*S3p[p][e]) / den.
// Block = 128 query rows (4 warps, lane = row); thread owns all 33 columns.
// S3p rows broadcast to all lanes; q reads conflict-free via stride 33.
__global__ __launch_bounds__(128) void kernelC(const float* __restrict__ q,
                                               float* __restrict__ out) {
    __shared__ float qs[128 * ESQ];        // 16.9 KB
    __shared__ float s3s[132 * ESS];       // 19.0 KB
    __shared__ float s2s[DD * ESS];        // 4.6 KB
    __shared__ float svs[DD];
    __shared__ unsigned pt[NPAIR];         // 2.1 KB

    const int bh = blockIdx.x;
    const int tid = threadIdx.x;
    const int growbase = blockIdx.y * 128;
    const float4* qb4 = (const float4*)(q + ((size_t)bh * NSEQ + growbase) * DD);

    // q tile: 128x32 -> stride-33 smem (scalar stores; one-time)
#pragma unroll
    for (int j = 0; j < 8; ++j) {
        int idx = j * 128 + tid;           // 1024 float4
        int r = idx >> 3, c = (idx & 7) * 4;
        float4 t4 = qb4[idx];
        qs[r * ESQ + c + 0] = t4.x; qs[r * ESQ + c + 1] = t4.y;
        qs[r * ESQ + c + 2] = t4.z; qs[r * ESQ + c + 3] = t4.w;
    }
    {
        const float4* s2g = (const float4*)(g_S2 + (size_t)bh * DD * ESS);
        for (int idx = tid; idx < (DD * ESS) / 4; idx += 128)
            ((float4*)s2s)[idx] = s2g[idx];
        if (tid < 8) ((float4*)svs)[tid] = ((const float4*)(g_sv + bh * DD))[tid];
    }
    if (tid < 32) {                         // pair table, f1 = tid
        int off = tid * 32 - tid * (tid - 1) / 2;
        for (int f2v = tid; f2v < 32; ++f2v)
            pt[off + f2v - tid] = (unsigned)(tid | (f2v << 8));
    }
    __syncthreads();

    const unsigned qoff = tid * ESQ;        // lane-private q row
    float4 c0 = {0,0,0,0}, c1 = {0,0,0,0}, c2 = {0,0,0,0}, c3 = {0,0,0,0};
    float4 c4 = {0,0,0,0}, c5 = {0,0,0,0}, c6 = {0,0,0,0}, c7 = {0,0,0,0};
    float den2 = 0.0f;

    for (int ch = 0; ch < 4; ++ch) {        // 528 pair-rows in 4 chunks of 132
        const float4* src = (const float4*)(g_S3p + ((size_t)bh * NPAIR_PAD + ch * 132) * ESS);
        for (int idx = tid; idx < (132 * ESS) / 4; idx += 128)
            ((float4*)s3s)[idx] = src[idx];
        __syncthreads();
        const int pbase = ch * 132;
#pragma unroll 2
        for (int pl = 0; pl < 132; ++pl) {
            const unsigned pr = pt[pbase + pl];
            const float a = qs[qoff + (pr & 255u)] * qs[qoff + (pr >> 8)];
            const float* r3 = s3s + pl * ESS;
            float4 b;
            b = *(const float4*)(r3 +  0); c0.x += a*b.x; c0.y += a*b.y; c0.z += a*b.z; c0.w += a*b.w;
            b = *(const float4*)(r3 +  4); c1.x += a*b.x; c1.y += a*b.y; c1.z += a*b.z; c1.w += a*b.w;
            b = *(const float4*)(r3 +  8); c2.x += a*b.x; c2.y += a*b.y; c2.z += a*b.z; c2.w += a*b.w;
            b = *(const float4*)(r3 + 12); c3.x += a*b.x; c3.y += a*b.y; c3.z += a*b.z; c3.w += a*b.w;
            b = *(const float4*)(r3 + 16); c4.x += a*b.x; c4.y += a*b.y; c4.z += a*b.z; c4.w += a*b.w;
            b = *(const float4*)(r3 + 20); c5.x += a*b.x; c5.y += a*b.y; c5.z += a*b.z; c5.w += a*b.w;
            b = *(const float4*)(r3 + 24); c6.x += a*b.x; c6.y += a*b.y; c6.z += a*b.z; c6.w += a*b.w;
            b = *(const float4*)(r3 + 28); c7.x += a*b.x; c7.y += a*b.y; c7.z += a*b.z; c7.w += a*b.w;
            den2 += a * r3[32];
        }
        __syncthreads();
    }

    // apply A2 = 0.5, then add the S2 (degree-1) term into the same regs
    c0.x *= 0.5f; c0.y *= 0.5f; c0.z *= 0.5f; c0.w *= 0.5f;
    c1.x *= 0.5f; c1.y *= 0.5f; c1.z *= 0.5f; c1.w *= 0.5f;
    c2.x *= 0.5f; c2.y *= 0.5f; c2.z *= 0.5f; c2.w *= 0.5f;
    c3.x *= 0.5f; c3.y *= 0.5f; c3.z *= 0.5f; c3.w *= 0.5f;
    c4.x *= 0.5f; c4.y *= 0.5f; c4.z *= 0.5f; c4.w *= 0.5f;
    c5.x *= 0.5f; c5.y *= 0.5f; c5.z *= 0.5f; c5.w *= 0.5f;
    c6.x *= 0.5f; c6.y *= 0.5f; c6.z *= 0.5f; c6.w *= 0.5f;
    c7.x *= 0.5f; c7.y *= 0.5f; c7.z *= 0.5f; c7.w *= 0.5f;
    den2 *= 0.5f;

#pragma unroll
    for (int d = 0; d < DD; ++d) {
        const float wq = qs[qoff + d];
        const float* r2 = s2s + d * ESS;
        float4 b;
        b = *(const float4*)(r2 +  0); c0.x += wq*b.x; c0.y += wq*b.y; c0.z += wq*b.z; c0.w += wq*b.w;
        b = *(const float4*)(r2 +  4); c1.x += wq*b.x; c1.y += wq*b.y; c1.z += wq*b.z; c1.w += wq*b.w;
        b = *(const float4*)(r2 +  8); c2.x += wq*b.x; c2.y += wq*b.y; c2.z += wq*b.z; c2.w += wq*b.w;
        b = *(const float4*)(r2 + 12); c3.x += wq*b.x; c3.y += wq*b.y; c3.z += wq*b.z; c3.w += wq*b.w;
        b = *(const float4*)(r2 + 16); c4.x += wq*b.x; c4.y += wq*b.y; c4.z += wq*b.z; c4.w += wq*b.w;
        b = *(const float4*)(r2 + 20); c5.x += wq*b.x; c5.y += wq*b.y; c5.z += wq*b.z; c5.w += wq*b.w;
        b = *(const float4*)(r2 + 24); c6.x += wq*b.x; c6.y += wq*b.y; c6.z += wq*b.z; c6.w += wq*b.w;
        b = *(const float4*)(r2 + 28); c7.x += wq*b.x; c7.y += wq*b.y; c7.z += wq*b.z; c7.w += wq*b.w;
        den2 += wq * r2[32];
    }

    const float inv = 1.0f / (4096.0f + den2);   // A0*N + ...
    float* ob = out + ((size_t)bh * NSEQ + growbase + tid) * DD;
    float4 o;
    o.x = (svs[ 0]+c0.x)*inv; o.y = (svs[ 1]+c0.y)*inv; o.z = (svs[ 2]+c0.z)*inv; o.w = (svs[ 3]+c0.w)*inv; *(float4*)(ob +  0) = o;
    o.x = (svs[ 4]+c1.x)*inv; o.y = (svs[ 5]+c1.y)*inv; o.z = (svs[ 6]+c1.z)*inv; o.w = (svs[ 7]+c1.w)*inv; *(float4*)(ob +  4) = o;
    o.x = (svs[ 8]+c2.x)*inv; o.y = (svs[ 9]+c2.y)*inv; o.z = (svs[10]+c2.z)*inv; o.w = (svs[11]+c2.w)*inv; *(float4*)(ob +  8) = o;
    o.x = (svs[12]+c3.x)*inv; o.y = (svs[13]+c3.y)*inv; o.z = (svs[14]+c3.z)*inv; o.w = (svs[15]+c3.w)*inv; *(float4*)(ob + 12) = o;
    o.x = (svs[16]+c4.x)*inv; o.y = (svs[17]+c4.y)*inv; o.z = (svs[18]+c4.z)*inv; o.w = (svs[19]+c4.w)*inv; *(float4*)(ob + 16) = o;
    o.x = (svs[20]+c5.x)*inv; o.y = (svs[21]+c5.y)*inv; o.z = (svs[22]+c5.z)*inv; o.w = (svs[23]+c5.w)*inv; *(float4*)(ob + 20) = o;
    o.x = (svs[24]+c6.x)*inv; o.y = (svs[25]+c6.y)*inv; o.z = (svs[26]+c6.z)*inv; o.w = (svs[27]+c6.w)*inv; *(float4*)(ob + 24) = o;
    o.x = (svs[28]+c7.x)*inv; o.y = (svs[29]+c7.y)*inv; o.z = (svs[30]+c7.z)*inv; o.w = (svs[31]+c7.w)*inv; *(float4*)(ob + 28) = o;
}

// ---------------------------------------------------------------- launch
extern "C" void kernel_launch(void* const* d_in, const int* in_sizes, int n_in,
                              void* d_out, int out_size) {
    const float* q = (const float*)d_in[0];
    const float* k = (const float*)d_in[1];
    const float* v = (const float*)d_in[2];
    float* out = (float*)d_out;
    (void)in_sizes; (void)n_in; (void)out_size;

    zero_kernel<<<(BH * NPAIR_PAD * ESS + 255) / 256, 256>>>();
    kernelA<<<dim3(BH, 8), 64>>>(k, v);
    kernelB<<<dim3(BH, 4, 17), 32>>>(k, v);
    kernelC<<<dim3(BH, NSEQ / 128), 128>>>(q, out);
}

// round 4
// speedup vs baseline: 2.6776x; 1.1038x over previous
#include <cuda_runtime.h>
#include <cuda_bf16.h>
#include <cstdint>

// FAST attention (p=2 Taylor linear attention) as two unified feature GEMMs
// on HMMA (mma.sync m16n8k16 bf16, fp32 accum, hi/lo split for accuracy).
//   Phi[n,F]: F=0 -> 1, F=1..32 -> x_d, F=33..560 -> pair products
//   Phase 1: M3[F,e] = sum_n PhiK_w[n,F] * Vaug[n,e]   (Vaug col32 = 1)
//   Phase 2: D[n,e]  = sum_F PhiQ[n,F]  * M3[F,e];  out = D[:,0:32]/D[:,32]
// PhiK_w carries all coefficients (A0=1, A1=1, A2*sym: diag 0.5 offdiag 1).

#define NBH   32
#define NSEQ  4096
#define DD    32
#define FTOT  561
#define FPAD  576
#define ENB   40          // padded N (covers 33 used cols)
#define ER    33          // stored M3 rows (e = 0..32)

// smem layout (bytes). Tile rows are 72 halves (144 B): 64 used + pad,
// 16B-aligned rows, conflict-free ldmatrix (36r mod 32 = 4r distinct r<8).
#define ASTR    144
#define OFF_ALO 18432     // A: 128 rows
#define OFF_B   36864     // B: 40 rows
#define OFF_BLO 5760
#define OFF_STG 48384     // staged k/q tile, fp32 [rows][35], col32 = 1.0
#define SM_PH1  (OFF_STG + 64 * 35 * 4)     // 57344
#define SM_PH2  (OFF_STG + 128 * 35 * 4)    // 66304

__device__ uint32_t       g_ptab[640];                 // a | b<<8 | wc<<16
__device__ float          g_M3p[2 * NBH * ER * FPAD];  // two n-half partials
__device__ __nv_bfloat16  g_M3hi[NBH * ER * FPAD];
__device__ __nv_bfloat16  g_M3lo[NBH * ER * FPAD];

// ---------------------------------------------------------------- helpers
__device__ __forceinline__ uint32_t smem_u32(const void* p) {
    uint32_t a;
    asm("{ .reg .u64 t; cvta.to.shared.u64 t, %1; cvt.u32.u64 %0, t; }" : "=r"(a) : "l"(p));
    return a;
}
// pack (v0,v1) -> bf16x2 hi, and residuals -> bf16x2 lo
__device__ __forceinline__ void split2(float v0, float v1, uint32_t& hp, uint32_t& lp) {
    asm("cvt.rn.bf16x2.f32 %0, %1, %2;" : "=r"(hp) : "f"(v1), "f"(v0));
    float h0 = __uint_as_float(hp << 16);
    float h1 = __uint_as_float(hp & 0xFFFF0000u);
    float r0 = v0 - h0, r1 = v1 - h1;
    asm("cvt.rn.bf16x2.f32 %0, %1, %2;" : "=r"(lp) : "f"(r1), "f"(r0));
}
__device__ __forceinline__ void ldm4(uint32_t a[4], uint32_t addr) {
    asm volatile("ldmatrix.sync.aligned.m8n8.x4.shared.b16 {%0,%1,%2,%3}, [%4];"
                 : "=r"(a[0]), "=r"(a[1]), "=r"(a[2]), "=r"(a[3]) : "r"(addr));
}
__device__ __forceinline__ void ldm2(uint32_t b[2], uint32_t addr) {
    asm volatile("ldmatrix.sync.aligned.m8n8.x2.shared.b16 {%0,%1}, [%2];"
                 : "=r"(b[0]), "=r"(b[1]) : "r"(addr));
}
__device__ __forceinline__ void mma16816(float c[4], const uint32_t a[4], const uint32_t b[2]) {
    asm volatile("mma.sync.aligned.m16n8k16.row.col.f32.bf16.bf16.f32 "
                 "{%0,%1,%2,%3}, {%4,%5,%6,%7}, {%8,%9}, {%0,%1,%2,%3};"
                 : "+f"(c[0]), "+f"(c[1]), "+f"(c[2]), "+f"(c[3])
                 : "r"(a[0]), "r"(a[1]), "r"(a[2]), "r"(a[3]), "r"(b[0]), "r"(b[1]));
}
// one K=64 chunk: 4 k-steps x 5 n-blocks x 3 split-mmas
__device__ __forceinline__ void mma_chunk(float c[5][4], uint32_t aBase, uint32_t bBase) {
#pragma unroll
    for (int ks = 0; ks < 4; ++ks) {
        uint32_t ah[4], al[4];
        ldm4(ah, aBase + ks * 32);
        ldm4(al, aBase + OFF_ALO + ks * 32);
#pragma unroll
        for (int nb = 0; nb < 5; ++nb) {
            uint32_t bhh[2], bll[2];
            ldm2(bhh, bBase + nb * 8 * ASTR + ks * 32);
            ldm2(bll, bBase + nb * 8 * ASTR + OFF_BLO + ks * 32);
            mma16816(c[nb], ah, bhh);
            mma16816(c[nb], ah, bll);
            mma16816(c[nb], al, bhh);
        }
    }
}

// ---------------------------------------------------------------- init table
__global__ void initTab() {
    int F = blockIdx.x * 256 + threadIdx.x;
    if (F >= 640) return;
    uint32_t a = 32, b = 32, wc = 0;                    // col 32 of stage = 1.0
    if (F == 0) wc = 2;                                 // w = 1
    else if (F < 33) { a = F - 1; b = 32; wc = 2; }     // linear
    else if (F < FTOT) {
        int p = F - 33, f1 = 0;
        while (p >= 32 - f1) { p -= 32 - f1; ++f1; }
        a = f1; b = f1 + p;
        wc = (a == b) ? 1 : 2;                          // A2*sym: 0.5 / 1.0
    }
    g_ptab[F] = a | (b << 8) | (wc << 16);
}

// ---------------------------------------------------------------- phase 1
// grid (NBH, 5 F-tiles, 2 n-halves), 256 threads = 8 warps (M=128 strip).
__global__ __launch_bounds__(256) void ph1(const float* __restrict__ k,
                                           const float* __restrict__ v) {
    extern __shared__ char sm[];
    float* kt = (float*)(sm + OFF_STG);                 // [64][35], col32 = 1
    const int bh = blockIdx.x, ft = blockIdx.y, nh = blockIdx.z;
    const int tid = threadIdx.x, wid = tid >> 5, lane = tid & 31;
    const int r = tid >> 1, ch = (tid & 1) * 32;
    const uint32_t smb = smem_u32(sm);

    const uint32_t tab = g_ptab[ft * 128 + r];
    const int fa = tab & 255, fb = (tab >> 8) & 255;
    const float w = 0.5f * (float)(tab >> 16);
    const float* kb = k + (size_t)bh * NSEQ * DD;
    const float* vb = v + (size_t)bh * NSEQ * DD;

    // constant B rows: row 32 = ones (hi), rows 33..39 = 0; lo = 0
    for (int i = tid; i < 8 * 36; i += 256) {
        int rr = 32 + i / 36, cc = i % 36;
        *(uint32_t*)(sm + OFF_B + rr * ASTR + cc * 4) =
            (rr == 32 && cc < 32) ? 0x3F803F80u : 0u;
        *(uint32_t*)(sm + OFF_B + OFF_BLO + rr * ASTR + cc * 4) = 0u;
    }

    const uint32_t aBase = smb + (wid * 16 + (lane & 15)) * ASTR + (lane >> 4) * 16;
    const uint32_t bBase = smb + OFF_B + (lane & 7) * ASTR + ((lane >> 3) & 1) * 16;

    float c[5][4] = {};
    for (int cc = 0; cc < 32; ++cc) {
        const int n0 = nh * 2048 + cc * 64;
        __syncthreads();                                // prev mma done
        // stage k tile [64][32] fp32 + ones col
        {
            int i2 = tid;
#pragma unroll
            for (int it = 0; it < 2; ++it, i2 += 256) {
                int rr = i2 >> 3, c4 = (i2 & 7) * 4;
                float4 t = *(const float4*)(kb + (size_t)(n0 + rr) * DD + c4);
                float* d = kt + rr * 35 + c4;
                d[0] = t.x; d[1] = t.y; d[2] = t.z; d[3] = t.w;
            }
            if (tid < 64) kt[tid * 35 + 32] = 1.0f;
        }
        // build B rows 0..31 (Vaug^T): item = (npair, e)
#pragma unroll
        for (int it = 0; it < 4; ++it) {
            int i = it * 256 + tid;
            int np = i >> 5, e = i & 31;
            float v0 = vb[(size_t)(n0 + 2 * np) * DD + e];
            float v1 = vb[(size_t)(n0 + 2 * np + 1) * DD + e];
            uint32_t hp, lp; split2(v0, v1, hp, lp);
            *(uint32_t*)(sm + OFF_B + e * ASTR + np * 4) = hp;
            *(uint32_t*)(sm + OFF_B + OFF_BLO + e * ASTR + np * 4) = lp;
        }
        __syncthreads();                                // kt ready
        // build A row r = weighted feature over n-cols ch..ch+31
#pragma unroll
        for (int j = 0; j < 32; j += 2) {
            const float* k0 = kt + (ch + j) * 35;
            const float* k1 = kt + (ch + j + 1) * 35;
            float v0 = w * k0[fa] * k0[fb];
            float v1 = w * k1[fa] * k1[fb];
            uint32_t hp, lp; split2(v0, v1, hp, lp);
            *(uint32_t*)(sm + r * ASTR + (ch + j) * 2) = hp;
            *(uint32_t*)(sm + OFF_ALO + r * ASTR + (ch + j) * 2) = lp;
        }
        __syncthreads();                                // A, B ready
        mma_chunk(c, aBase, bBase);
    }

    // epilogue: direct stores (two disjoint partial buffers, no atomics)
    float* dst = g_M3p + (size_t)nh * (NBH * ER * FPAD) + (size_t)bh * ER * FPAD;
    const int Fg = ft * 128 + wid * 16 + (lane >> 2);
#pragma unroll
    for (int nb = 0; nb < 5; ++nb) {
        const int e = nb * 8 + (lane & 3) * 2;
        if (nb < 4) {
            if (Fg < FPAD) {
                if (Fg < FTOT) {
                    dst[(size_t)e * FPAD + Fg] = c[nb][0];
                    dst[(size_t)(e + 1) * FPAD + Fg] = c[nb][1];
                }
                if (Fg + 8 < FTOT) {
                    dst[(size_t)e * FPAD + Fg + 8] = c[nb][2];
                    dst[(size_t)(e + 1) * FPAD + Fg + 8] = c[nb][3];
                }
            }
        } else if ((lane & 3) == 0 && Fg < FPAD) {
            if (Fg < FTOT)     dst[(size_t)32 * FPAD + Fg] = c[4][0];
            if (Fg + 8 < FTOT) dst[(size_t)32 * FPAD + Fg + 8] = c[4][2];
        }
    }
}

// ---------------------------------------------------------------- combine+cvt
__global__ void cvtM3(const float zero_pad) {
    size_t i = (size_t)blockIdx.x * 256 + threadIdx.x;  // < 32*33*576
    // pad columns (F in [561,576)) were never written: mask them to 0
    int F = (int)(i % FPAD);
    float val = (F < FTOT) ? (g_M3p[i] + g_M3p[(size_t)NBH * ER * FPAD + i]) : zero_pad;
    __nv_bfloat16 h = __float2bfloat16(val);
    g_M3hi[i] = h;
    g_M3lo[i] = __float2bfloat16(val - __bfloat162float(h));
}

// ---------------------------------------------------------------- phase 2
// grid (NBH, 32 n-tiles), 256 threads.
__global__ __launch_bounds__(256) void ph2(const float* __restrict__ q,
                                           float* __restrict__ out) {
    extern __shared__ char sm[];
    float* qs = (float*)(sm + OFF_STG);                 // [128][35], col32 = 1
    const int bh = blockIdx.x, nt = blockIdx.y;
    const int tid = threadIdx.x, wid = tid >> 5, lane = tid & 31;
    const int r = tid >> 1, ch = (tid & 1) * 32;
    const uint32_t smb = smem_u32(sm);

    // stage q tile [128][32] + ones col
    {
        const float4* qb4 = (const float4*)(q + ((size_t)bh * NSEQ + nt * 128) * DD);
        int i2 = tid;
#pragma unroll
        for (int it = 0; it < 4; ++it, i2 += 256) {
            int rr = i2 >> 3, c4 = (i2 & 7) * 4;
            float4 t = qb4[i2];
            float* d = qs + rr * 35 + c4;
            d[0] = t.x; d[1] = t.y; d[2] = t.z; d[3] = t.w;
        }
        if (tid < 128) qs[tid * 35 + 32] = 1.0f;
    }
    // B rows 33..39 = 0 (hi & lo), once
    for (int i = tid; i < 7 * 36; i += 256) {
        int rr = 33 + i / 36, ccx = i % 36;
        *(uint32_t*)(sm + OFF_B + rr * ASTR + ccx * 4) = 0u;
        *(uint32_t*)(sm + OFF_B + OFF_BLO + rr * ASTR + ccx * 4) = 0u;
    }
    __syncthreads();

    const uint32_t aBase = smb + (wid * 16 + (lane & 15)) * ASTR + (lane >> 4) * 16;
    const uint32_t bBase = smb + OFF_B + (lane & 7) * ASTR + ((lane >> 3) & 1) * 16;
    const __nv_bfloat16* mh = g_M3hi + (size_t)bh * ER * FPAD;
    const __nv_bfloat16* ml = g_M3lo + (size_t)bh * ER * FPAD;

    float c[5][4] = {};
    for (int cc = 0; cc < 9; ++cc) {
        const int f0 = cc * 64;
        // build B rows 0..32: copy 64-half slices of M3 hi/lo
        for (int i = tid; i < ER * 32; i += 256) {
            int e = i >> 5, j = i & 31;
            *(uint32_t*)(sm + OFF_B + e * ASTR + j * 4) =
                *(const uint32_t*)((const char*)(mh + (size_t)e * FPAD + f0) + j * 4);
            *(uint32_t*)(sm + OFF_B + OFF_BLO + e * ASTR + j * 4) =
                *(const uint32_t*)((const char*)(ml + (size_t)e * FPAD + f0) + j * 4);
        }
        // build A row r: PhiQ features f0+ch+j
        const float* qr = qs + r * 35;
#pragma unroll
        for (int j = 0; j < 32; j += 2) {
            uint32_t t0 = g_ptab[f0 + ch + j];
            uint32_t t1 = g_ptab[f0 + ch + j + 1];
            float v0 = (t0 >> 16) ? qr[t0 & 255] * qr[(t0 >> 8) & 255] : 0.0f;
            float v1 = (t1 >> 16) ? qr[t1 & 255] * qr[(t1 >> 8) & 255] : 0.0f;
            uint32_t hp, lp; split2(v0, v1, hp, lp);
            *(uint32_t*)(sm + r * ASTR + (ch + j) * 2) = hp;
            *(uint32_t*)(sm + OFF_ALO + r * ASTR + (ch + j) * 2) = lp;
        }
        __syncthreads();                                // A, B ready
        mma_chunk(c, aBase, bBase);
        __syncthreads();                                // mma done before rebuild
    }

    // epilogue: divide by den (col 32 = n-block 4, col 0, lanes t%4==0)
    const float dl = __shfl_sync(0xFFFFFFFFu, c[4][0], lane & ~3);
    const float dh = __shfl_sync(0xFFFFFFFFu, c[4][2], lane & ~3);
    const float il = 1.0f / dl, ih = 1.0f / dh;
    const int row = nt * 128 + wid * 16 + (lane >> 2);
    float* ob = out + ((size_t)bh * NSEQ + row) * DD;
#pragma unroll
    for (int nb = 0; nb < 4; ++nb) {
        const int e = nb * 8 + (lane & 3) * 2;
        float2 lo2 = { c[nb][0] * il, c[nb][1] * il };
        float2 hi2 = { c[nb][2] * ih, c[nb][3] * ih };
        *(float2*)(ob + e) = lo2;
        *(float2*)(ob + 8 * DD + e) = hi2;              // row + 8
    }
}

// ---------------------------------------------------------------- launch
extern "C" void kernel_launch(void* const* d_in, const int* in_sizes, int n_in,
                              void* d_out, int out_size) {
    const float* q = (const float*)d_in[0];
    const float* k = (const float*)d_in[1];
    const float* v = (const float*)d_in[2];
    float* out = (float*)d_out;
    (void)in_sizes; (void)n_in; (void)out_size;

    cudaFuncSetAttribute(ph1, cudaFuncAttributeMaxDynamicSharedMemorySize, SM_PH1);
    cudaFuncSetAttribute(ph2, cudaFuncAttributeMaxDynamicSharedMemorySize, SM_PH2);

    initTab<<<3, 256>>>();
    ph1<<<dim3(NBH, 5, 2), 256, SM_PH1>>>(k, v);
    cvtM3<<<(NBH * ER * FPAD) / 256, 256>>>(0.0f);
    ph2<<<dim3(NBH, 32), 256, SM_PH2>>>(q, out);
}

// round 5
// speedup vs baseline: 5.1740x; 1.9323x over previous
#include <cuda_runtime.h>
#include <cuda_bf16.h>
#include <cstdint>

// FAST attention (p=2 Taylor linear attention) as two unified feature GEMMs
// on HMMA (mma.sync m16n8k16 bf16, fp32 accum, hi/lo split: 3 MMAs).
//   Phi[n,F]: F=0 -> 1, F=1..32 -> x_d, F=33..560 -> pair products
//   Phase 1: M3[F,e] = sum_n PhiK_w[n,F] * Vaug[n,e]   (Vaug col32 = 1)
//   Phase 2: D[n,e]  = sum_F PhiQ[n,F]  * M3[F,e];  out = D[:,0:32]/D[:,32]
// A fragments are computed directly in registers (no A smem round-trip).
// Feature table stores byte offsets; pad features point at a zero column.

#define NBH   32
#define NSEQ  4096
#define DD    32
#define FTOT  561
#define FPAD  576
#define ER    33

#define KSTR  140          // staged fp32 tile row stride bytes (35 floats)
#define BSTR  144          // B row stride bytes (64 halves + pad)
#define BROWS 34           // 33 real + 1 zero row
#define BHALF (BROWS * BSTR)          // 4896  (hi or lo)
#define BBUF  (2 * BHALF)             // 9792  (hi + lo)

__device__ uint32_t g_ptab4[640];     // (a*4) | (b*4 << 16); pad -> col 33
__device__ float    g_wtab[640];      // ph1 row weight (A0/A1/A2*sym), pad 0
__device__ float          g_M3p[2 * NBH * ER * FPAD];
__device__ __nv_bfloat16  g_M3hi[NBH * ER * FPAD];
__device__ __nv_bfloat16  g_M3lo[NBH * ER * FPAD];

// ---------------------------------------------------------------- helpers
__device__ __forceinline__ uint32_t smem_u32(const void* p) {
    uint32_t a;
    asm("{ .reg .u64 t; cvta.to.shared.u64 t, %1; cvt.u32.u64 %0, t; }" : "=r"(a) : "l"(p));
    return a;
}
__device__ __forceinline__ void split2(float v0, float v1, uint32_t& hp, uint32_t& lp) {
    asm("cvt.rn.bf16x2.f32 %0, %1, %2;" : "=r"(hp) : "f"(v1), "f"(v0));
    float h0 = __uint_as_float(hp << 16);
    float h1 = __uint_as_float(hp & 0xFFFF0000u);
    asm("cvt.rn.bf16x2.f32 %0, %1, %2;" : "=r"(lp) : "f"(v1 - h1), "f"(v0 - h0));
}
__device__ __forceinline__ void ldm2(uint32_t b[2], uint32_t addr) {
    asm volatile("ldmatrix.sync.aligned.m8n8.x2.shared.b16 {%0,%1}, [%2];"
                 : "=r"(b[0]), "=r"(b[1]) : "r"(addr));
}
__device__ __forceinline__ void mma16816(float c[4], const uint32_t a[4], const uint32_t b[2]) {
    asm volatile("mma.sync.aligned.m16n8k16.row.col.f32.bf16.bf16.f32 "
                 "{%0,%1,%2,%3}, {%4,%5,%6,%7}, {%8,%9}, {%0,%1,%2,%3};"
                 : "+f"(c[0]), "+f"(c[1]), "+f"(c[2]), "+f"(c[3])
                 : "r"(a[0]), "r"(a[1]), "r"(a[2]), "r"(a[3]), "r"(b[0]), "r"(b[1]));
}

// ---------------------------------------------------------------- init table
__global__ void initTab() {
    int F = blockIdx.x * 256 + threadIdx.x;
    if (F >= 640) return;
    int a = 33, b = 33;
    float w = 0.0f;
    if (F == 0) { a = 32; b = 32; w = 1.0f; }
    else if (F < 33) { a = F - 1; b = 32; w = 1.0f; }
    else if (F < FTOT) {
        int p = F - 33, f1 = 0;
        while (p >= 32 - f1) { p -= 32 - f1; ++f1; }
        a = f1; b = f1 + p;
        w = (a == b) ? 0.5f : 1.0f;
    }
    g_ptab4[F] = (uint32_t)(a * 4) | ((uint32_t)(b * 4) << 16);
    g_wtab[F] = w;
}

// ---------------------------------------------------------------- phase 1
// grid (NBH, 5 F-tiles, 2 n-halves). A (PhiK_w) fragments in registers from a
// staged fp32 k-tile; B = Vaug^T split, double-buffered; one sync per chunk.
__global__ __launch_bounds__(256, 4) void ph1(const float* __restrict__ k,
                                              const float* __restrict__ v) {
    __shared__ __align__(16) char sm[2 * 64 * KSTR + 2 * BBUF];   // 37504 B
    const int OFF_B = 2 * 64 * KSTR;                               // 17920
    const int bh = blockIdx.x, ft = blockIdx.y, nh = blockIdx.z;
    const int tid = threadIdx.x, wid = tid >> 5, lane = tid & 31;
    const uint32_t smb = smem_u32(sm);

    const float* kb = k + (size_t)bh * NSEQ * DD;
    const float* vb = v + (size_t)bh * NSEQ * DD;

    // per-thread A row params (2 rows: F1 = base+g, F2 = F1+8)
    const int F1 = ft * 128 + wid * 16 + (lane >> 2);
    const uint32_t p1 = g_ptab4[F1], p2 = g_ptab4[F1 + 8];
    const float w1 = g_wtab[F1], w2 = g_wtab[F1 + 8];
    const uint32_t ao1 = p1 & 0xFFFFu, bo1 = p1 >> 16;
    const uint32_t ao2 = p2 & 0xFFFFu, bo2 = p2 >> 16;

    // init: kt cols 32..34 (both bufs), B rows 32 (ones hi) & 33 (zero), both bufs
    if (tid < 128) {
        float* r = (float*)(sm + (tid >> 6) * 64 * KSTR + (tid & 63) * KSTR);
        r[32] = 1.0f; r[33] = 0.0f; r[34] = 0.0f;
    }
    for (int i = tid; i < 2 * 2 * 2 * 36; i += 256) {      // buf, hi/lo, row32/33
        int b = i / 144, rem = i % 144;
        int reg = rem / 72, rr = 32 + (rem % 72) / 36, w = rem % 36;
        uint32_t val = (reg == 0 && rr == 32) ? 0x3F803F80u : 0u;
        *(uint32_t*)(sm + OFF_B + b * BBUF + reg * BHALF + rr * BSTR + w * 4) = val;
    }

    // per-lane B row offsets (rows clamp to zero row 33)
    uint32_t rowoff[5];
#pragma unroll
    for (int nb = 0; nb < 5; ++nb) {
        int e = nb * 8 + (lane & 7);
        rowoff[nb] = (uint32_t)((e < 33 ? e : 33) * BSTR + ((lane >> 3) & 1) * 16);
    }

    float c[5][4] = {};
    const int c0b = (lane & 3) * 2;

    for (int cc = 0; cc < 32; ++cc) {
        const int buf = cc & 1;
        const int n0 = nh * 2048 + cc * 64;
        const uint32_t ktb = smb + buf * 64 * KSTR;
        const uint32_t bbB = smb + OFF_B + buf * BBUF;

        // stage k tile [64][32] fp32
        {
            int i2 = tid;
#pragma unroll
            for (int it = 0; it < 2; ++it, i2 += 256) {
                int rr = i2 >> 3, c4 = (i2 & 7) * 4;
                float4 t = *(const float4*)(kb + (size_t)(n0 + rr) * DD + c4);
                float* d = (float*)(sm + buf * 64 * KSTR + rr * KSTR) + c4;
                d[0] = t.x; d[1] = t.y; d[2] = t.z; d[3] = t.w;
            }
        }
        // build B rows 0..31 (Vaug^T, split)
#pragma unroll
        for (int it = 0; it < 4; ++it) {
            int i = it * 256 + tid;
            int np = i >> 5, e = i & 31;
            float v0 = vb[(size_t)(n0 + 2 * np) * DD + e];
            float v1 = vb[(size_t)(n0 + 2 * np) * DD + DD + e];
            uint32_t hp, lp; split2(v0, v1, hp, lp);
            *(uint32_t*)(sm + OFF_B + buf * BBUF + e * BSTR + np * 4) = hp;
            *(uint32_t*)(sm + OFF_B + buf * BBUF + BHALF + e * BSTR + np * 4) = lp;
        }
        __syncthreads();

#pragma unroll
        for (int ks = 0; ks < 4; ++ks) {
            const int c0 = ks * 16 + c0b;
            uint32_t ah[4], al[4];
            {
                const uint32_t pr0 = ktb + (uint32_t)(c0 * KSTR);
                const uint32_t pr1 = pr0 + KSTR;
                const uint32_t pr8 = pr0 + 8 * KSTR;
                const uint32_t pr9 = pr8 + KSTR;
                float x0, x1, y0, y1;
                // row F1
                asm("ld.shared.f32 %0, [%1];" : "=f"(x0) : "r"(pr0 + ao1));
                asm("ld.shared.f32 %0, [%1];" : "=f"(x1) : "r"(pr0 + bo1));
                asm("ld.shared.f32 %0, [%1];" : "=f"(y0) : "r"(pr1 + ao1));
                asm("ld.shared.f32 %0, [%1];" : "=f"(y1) : "r"(pr1 + bo1));
                split2(w1 * x0 * x1, w1 * y0 * y1, ah[0], al[0]);
                asm("ld.shared.f32 %0, [%1];" : "=f"(x0) : "r"(pr8 + ao1));
                asm("ld.shared.f32 %0, [%1];" : "=f"(x1) : "r"(pr8 + bo1));
                asm("ld.shared.f32 %0, [%1];" : "=f"(y0) : "r"(pr9 + ao1));
                asm("ld.shared.f32 %0, [%1];" : "=f"(y1) : "r"(pr9 + bo1));
                split2(w1 * x0 * x1, w1 * y0 * y1, ah[2], al[2]);
                // row F2
                asm("ld.shared.f32 %0, [%1];" : "=f"(x0) : "r"(pr0 + ao2));
                asm("ld.shared.f32 %0, [%1];" : "=f"(x1) : "r"(pr0 + bo2));
                asm("ld.shared.f32 %0, [%1];" : "=f"(y0) : "r"(pr1 + ao2));
                asm("ld.shared.f32 %0, [%1];" : "=f"(y1) : "r"(pr1 + bo2));
                split2(w2 * x0 * x1, w2 * y0 * y1, ah[1], al[1]);
                asm("ld.shared.f32 %0, [%1];" : "=f"(x0) : "r"(pr8 + ao2));
                asm("ld.shared.f32 %0, [%1];" : "=f"(x1) : "r"(pr8 + bo2));
                asm("ld.shared.f32 %0, [%1];" : "=f"(y0) : "r"(pr9 + ao2));
                asm("ld.shared.f32 %0, [%1];" : "=f"(y1) : "r"(pr9 + bo2));
                split2(w2 * x0 * x1, w2 * y0 * y1, ah[3], al[3]);
            }
#pragma unroll
            for (int nb = 0; nb < 5; ++nb) {
                uint32_t bhh[2], bll[2];
                ldm2(bhh, bbB + rowoff[nb] + ks * 32);
                ldm2(bll, bbB + BHALF + rowoff[nb] + ks * 32);
                mma16816(c[nb], ah, bhh);
                mma16816(c[nb], ah, bll);
                mma16816(c[nb], al, bhh);
            }
        }
    }

    // epilogue: two disjoint partial buffers, no atomics
    float* dst = g_M3p + (size_t)nh * (NBH * ER * FPAD) + (size_t)bh * ER * FPAD;
    const int Fg = F1;
#pragma unroll
    for (int nb = 0; nb < 5; ++nb) {
        const int e = nb * 8 + (lane & 3) * 2;
        if (nb < 4) {
            if (Fg < FTOT) {
                dst[(size_t)e * FPAD + Fg] = c[nb][0];
                dst[(size_t)(e + 1) * FPAD + Fg] = c[nb][1];
            }
            if (Fg + 8 < FTOT) {
                dst[(size_t)e * FPAD + Fg + 8] = c[nb][2];
                dst[(size_t)(e + 1) * FPAD + Fg + 8] = c[nb][3];
            }
        } else if ((lane & 3) == 0) {
            if (Fg < FTOT)     dst[(size_t)32 * FPAD + Fg] = c[4][0];
            if (Fg + 8 < FTOT) dst[(size_t)32 * FPAD + Fg + 8] = c[4][2];
        }
    }
}

// ---------------------------------------------------------------- combine+cvt
__global__ void cvtM3() {
    size_t i = (size_t)blockIdx.x * 256 + threadIdx.x;
    int F = (int)(i % FPAD);
    float val = (F < FTOT) ? (g_M3p[i] + g_M3p[(size_t)NBH * ER * FPAD + i]) : 0.0f;
    __nv_bfloat16 h = __float2bfloat16(val);
    g_M3hi[i] = h;
    g_M3lo[i] = __float2bfloat16(val - __bfloat162float(h));
}

// ---------------------------------------------------------------- phase 2
// grid (NBH, 32 n-tiles). A (PhiQ) fragments in registers from staged q tile;
// B = M3 hi/lo slices, double-buffered; one sync per chunk.
__global__ __launch_bounds__(256, 4) void ph2(const float* __restrict__ q,
                                              float* __restrict__ out) {
    __shared__ __align__(16) char sm[128 * KSTR + 2560 + 2 * BBUF];   // 40064 B
    const int OFF_TAB = 128 * KSTR;            // 17920
    const int OFF_B = OFF_TAB + 2560;          // 20480
    const int bh = blockIdx.x, nt = blockIdx.y;
    const int tid = threadIdx.x, wid = tid >> 5, lane = tid & 31;
    const uint32_t smb = smem_u32(sm);

    // stage q tile [128][32] + cols 32..34 = {1,0,0}; copy table
    {
        const float4* qb4 = (const float4*)(q + ((size_t)bh * NSEQ + nt * 128) * DD);
        int i2 = tid;
#pragma unroll
        for (int it = 0; it < 4; ++it, i2 += 256) {
            int rr = i2 >> 3, c4 = (i2 & 7) * 4;
            float4 t = qb4[i2];
            float* d = (float*)(sm + rr * KSTR) + c4;
            d[0] = t.x; d[1] = t.y; d[2] = t.z; d[3] = t.w;
        }
        if (tid < 128) {
            float* r = (float*)(sm + tid * KSTR);
            r[32] = 1.0f; r[33] = 0.0f; r[34] = 0.0f;
        }
        for (int i = tid; i < 640; i += 256)
            *(uint32_t*)(sm + OFF_TAB + i * 4) = g_ptab4[i];
        for (int i = tid; i < 2 * 2 * 36; i += 256) {       // zero row 33, both bufs hi/lo
            int b = i / 72, reg = (i % 72) / 36, w = i % 36;
            *(uint32_t*)(sm + OFF_B + b * BBUF + reg * BHALF + 33 * BSTR + w * 4) = 0u;
        }
    }

    uint32_t rowoff[5];
#pragma unroll
    for (int nb = 0; nb < 5; ++nb) {
        int e = nb * 8 + (lane & 7);
        rowoff[nb] = (uint32_t)((e < 33 ? e : 33) * BSTR + ((lane >> 3) & 1) * 16);
    }

    const uint32_t q1 = smb + (uint32_t)((wid * 16 + (lane >> 2)) * KSTR);
    const uint32_t q2 = q1 + 8 * KSTR;
    const int c0b = (lane & 3) * 2;
    const __nv_bfloat16* mh = g_M3hi + (size_t)bh * ER * FPAD;
    const __nv_bfloat16* ml = g_M3lo + (size_t)bh * ER * FPAD;

    float c[5][4] = {};

    for (int cc = 0; cc < 9; ++cc) {
        const int buf = cc & 1;
        const int f0 = cc * 64;
        const uint32_t bbB = smb + OFF_B + buf * BBUF;

        // build B rows 0..32 from M3 slices
        for (int i = tid; i < ER * 32; i += 256) {
            int e = i >> 5, j = i & 31;
            *(uint32_t*)(sm + OFF_B + buf * BBUF + e * BSTR + j * 4) =
                *(const uint32_t*)((const char*)(mh + (size_t)e * FPAD + f0) + j * 4);
            *(uint32_t*)(sm + OFF_B + buf * BBUF + BHALF + e * BSTR + j * 4) =
                *(const uint32_t*)((const char*)(ml + (size_t)e * FPAD + f0) + j * 4);
        }
        __syncthreads();

#pragma unroll
        for (int ks = 0; ks < 4; ++ks) {
            const int c0 = f0 + ks * 16 + c0b;
            uint32_t ah[4], al[4];
            {
                uint32_t t0, t1, t8, t9;
                asm("ld.shared.b32 %0, [%1];" : "=r"(t0) : "r"(smb + OFF_TAB + c0 * 4));
                asm("ld.shared.b32 %0, [%1];" : "=r"(t1) : "r"(smb + OFF_TAB + c0 * 4 + 4));
                asm("ld.shared.b32 %0, [%1];" : "=r"(t8) : "r"(smb + OFF_TAB + c0 * 4 + 32));
                asm("ld.shared.b32 %0, [%1];" : "=r"(t9) : "r"(smb + OFF_TAB + c0 * 4 + 36));
                float xa, xb, ya, yb;
                // cols c0, c0+1
                asm("ld.shared.f32 %0, [%1];" : "=f"(xa) : "r"(q1 + (t0 & 0xFFFFu)));
                asm("ld.shared.f32 %0, [%1];" : "=f"(xb) : "r"(q1 + (t0 >> 16)));
                asm("ld.shared.f32 %0, [%1];" : "=f"(ya) : "r"(q1 + (t1 & 0xFFFFu)));
                asm("ld.shared.f32 %0, [%1];" : "=f"(yb) : "r"(q1 + (t1 >> 16)));
                split2(xa * xb, ya * yb, ah[0], al[0]);
                asm("ld.shared.f32 %0, [%1];" : "=f"(xa) : "r"(q2 + (t0 & 0xFFFFu)));
                asm("ld.shared.f32 %0, [%1];" : "=f"(xb) : "r"(q2 + (t0 >> 16)));
                asm("ld.shared.f32 %0, [%1];" : "=f"(ya) : "r"(q2 + (t1 & 0xFFFFu)));
                asm("ld.shared.f32 %0, [%1];" : "=f"(yb) : "r"(q2 + (t1 >> 16)));
                split2(xa * xb, ya * yb, ah[1], al[1]);
                // cols c0+8, c0+9
                asm("ld.shared.f32 %0, [%1];" : "=f"(xa) : "r"(q1 + (t8 & 0xFFFFu)));
                asm("ld.shared.f32 %0, [%1];" : "=f"(xb) : "r"(q1 + (t8 >> 16)));
                asm("ld.shared.f32 %0, [%1];" : "=f"(ya) : "r"(q1 + (t9 & 0xFFFFu)));
                asm("ld.shared.f32 %0, [%1];" : "=f"(yb) : "r"(q1 + (t9 >> 16)));
                split2(xa * xb, ya * yb, ah[2], al[2]);
                asm("ld.shared.f32 %0, [%1];" : "=f"(xa) : "r"(q2 + (t8 & 0xFFFFu)));
                asm("ld.shared.f32 %0, [%1];" : "=f"(xb) : "r"(q2 + (t8 >> 16)));
                asm("ld.shared.f32 %0, [%1];" : "=f"(ya) : "r"(q2 + (t9 & 0xFFFFu)));
                asm("ld.shared.f32 %0, [%1];" : "=f"(yb) : "r"(q2 + (t9 >> 16)));
                split2(xa * xb, ya * yb, ah[3], al[3]);
            }
#pragma unroll
            for (int nb = 0; nb < 5; ++nb) {
                uint32_t bhh[2], bll[2];
                ldm2(bhh, bbB + rowoff[nb] + ks * 32);
                ldm2(bll, bbB + BHALF + rowoff[nb] + ks * 32);
                mma16816(c[nb], ah, bhh);
                mma16816(c[nb], ah, bll);
                mma16816(c[nb], al, bhh);
            }
        }
    }

    // epilogue: divide by den (e=32 col lives in nb=4, C col 0 -> lanes l%4==0)
    const float dl = __shfl_sync(0xFFFFFFFFu, c[4][0], lane & ~3);
    const float dh = __shfl_sync(0xFFFFFFFFu, c[4][2], lane & ~3);
    const float il = 1.0f / dl, ih = 1.0f / dh;
    const int row = nt * 128 + wid * 16 + (lane >> 2);
    float* ob = out + ((size_t)bh * NSEQ + row) * DD;
#pragma unroll
    for (int nb = 0; nb < 4; ++nb) {
        const int e = nb * 8 + (lane & 3) * 2;
        float2 lo2 = { c[nb][0] * il, c[nb][1] * il };
        float2 hi2 = { c[nb][2] * ih, c[nb][3] * ih };
        *(float2*)(ob + e) = lo2;
        *(float2*)(ob + 8 * DD + e) = hi2;
    }
}

// ---------------------------------------------------------------- launch
extern "C" void kernel_launch(void* const* d_in, const int* in_sizes, int n_in,
                              void* d_out, int out_size) {
    const float* q = (const float*)d_in[0];
    const float* k = (const float*)d_in[1];
    const float* v = (const float*)d_in[2];
    float* out = (float*)d_out;
    (void)in_sizes; (void)n_in; (void)out_size;

    initTab<<<3, 256>>>();
    ph1<<<dim3(NBH, 5, 2), 256>>>(k, v);
    cvtM3<<<(NBH * ER * FPAD) / 256, 256>>>();
    ph2<<<dim3(NBH, 32), 256>>>(q, out);
}

// round 6
// speedup vs baseline: 6.2092x; 1.2001x over previous
#include <cuda_runtime.h>
#include <cuda_fp16.h>
#include <cstdint>

// FAST attention (p=2 Taylor linear attention) as two unified feature GEMMs
// on HMMA fp16 (mma.sync m16n8k16, fp32 accum).
//   Phi[n,F]: F=0 -> 1, F=1..32 -> x_d, F=33..560 -> pair products
//   Phase 1: M3[F,e] = sum_n PhiK_w[n,F] * Vaug[n,e]  -- full hi/lo split
//            (3 MMAs) => M3 near-exact; stored as single fp16 (2^-12).
//   Phase 2: D[n,e]  = sum_F PhiQ[n,F] * M3[F,e]; out = D[:,0:32]/D[:,32]
//            A single fp16, B single fp16 => 1 MMA per (ks,nb).
// PhiK_w carries all coefficients (A0=1, A1=1, A2*sym: diag 0.5 offdiag 1).

#define NBH   32
#define NSEQ  4096
#define DD    32
#define FTOT  561
#define FPAD  576
#define ER    33

#define KSTR  140          // staged fp32 tile row stride bytes (35 floats)
#define BSTR  144          // B row stride bytes (64 halves + pad)
#define BROWS 34           // 33 real + 1 zero row
#define BHALF (BROWS * BSTR)          // 4896
#define BBUF  (2 * BHALF)             // 9792 (hi + lo, ph1 only)

__device__ uint32_t g_ptab4[640];     // (a*4) | (b*4 << 16); pad -> col 33
__device__ float    g_wtab[640];      // ph1 row weight, pad 0
__device__ float    g_M3p[4 * NBH * ER * FPAD];     // 4 n-quarter partials
__device__ __half   g_M3h[NBH * ER * FPAD];

// ---------------------------------------------------------------- helpers
__device__ __forceinline__ uint32_t smem_u32(const void* p) {
    uint32_t a;
    asm("{ .reg .u64 t; cvta.to.shared.u64 t, %1; cvt.u32.u64 %0, t; }" : "=r"(a) : "l"(p));
    return a;
}
__device__ __forceinline__ uint32_t packH2(float v0, float v1) {
    uint32_t r;
    asm("cvt.rn.f16x2.f32 %0, %1, %2;" : "=r"(r) : "f"(v1), "f"(v0));  // lo=v0
    return r;
}
__device__ __forceinline__ void splitH2(float v0, float v1, uint32_t& hp, uint32_t& lp) {
    asm("cvt.rn.f16x2.f32 %0, %1, %2;" : "=r"(hp) : "f"(v1), "f"(v0));
    __half2 hh = *reinterpret_cast<__half2*>(&hp);
    float h0 = __low2float(hh), h1 = __high2float(hh);
    asm("cvt.rn.f16x2.f32 %0, %1, %2;" : "=r"(lp) : "f"(v1 - h1), "f"(v0 - h0));
}
__device__ __forceinline__ void ldm2(uint32_t b[2], uint32_t addr) {
    asm volatile("ldmatrix.sync.aligned.m8n8.x2.shared.b16 {%0,%1}, [%2];"
                 : "=r"(b[0]), "=r"(b[1]) : "r"(addr));
}
__device__ __forceinline__ void ldm4(uint32_t b[4], uint32_t addr) {
    asm volatile("ldmatrix.sync.aligned.m8n8.x4.shared.b16 {%0,%1,%2,%3}, [%4];"
                 : "=r"(b[0]), "=r"(b[1]), "=r"(b[2]), "=r"(b[3]) : "r"(addr));
}
__device__ __forceinline__ void mmaH(float c[4], const uint32_t a[4], const uint32_t b[2]) {
    asm volatile("mma.sync.aligned.m16n8k16.row.col.f32.f16.f16.f32 "
                 "{%0,%1,%2,%3}, {%4,%5,%6,%7}, {%8,%9}, {%0,%1,%2,%3};"
                 : "+f"(c[0]), "+f"(c[1]), "+f"(c[2]), "+f"(c[3])
                 : "r"(a[0]), "r"(a[1]), "r"(a[2]), "r"(a[3]), "r"(b[0]), "r"(b[1]));
}

// ---------------------------------------------------------------- init table
__global__ void initTab() {
    int F = blockIdx.x * 256 + threadIdx.x;
    if (F >= 640) return;
    int a = 33, b = 33;
    float w = 0.0f;
    if (F == 0) { a = 32; b = 32; w = 1.0f; }
    else if (F < 33) { a = F - 1; b = 32; w = 1.0f; }
    else if (F < FTOT) {
        int p = F - 33, f1 = 0;
        while (p >= 32 - f1) { p -= 32 - f1; ++f1; }
        a = f1; b = f1 + p;
        w = (a == b) ? 0.5f : 1.0f;
    }
    g_ptab4[F] = (uint32_t)(a * 4) | ((uint32_t)(b * 4) << 16);
    g_wtab[F] = w;
}

// ---------------------------------------------------------------- phase 1
// grid (NBH, 5 F-tiles, 4 n-quarters). A (PhiK_w) fp16 hi/lo in registers;
// B = Vaug^T fp16 hi/lo; 3 MMAs; double-buffered; one sync per chunk.
__global__ __launch_bounds__(256, 4) void ph1(const float* __restrict__ k,
                                              const float* __restrict__ v) {
    __shared__ __align__(16) char sm[2 * 64 * KSTR + 2 * BBUF];   // 37504 B
    const int OFF_B = 2 * 64 * KSTR;                               // 17920
    const int bh = blockIdx.x, ft = blockIdx.y, nh = blockIdx.z;
    const int tid = threadIdx.x, wid = tid >> 5, lane = tid & 31;
    const uint32_t smb = smem_u32(sm);

    const float* kb = k + (size_t)bh * NSEQ * DD;
    const float* vb = v + (size_t)bh * NSEQ * DD;

    const int F1 = ft * 128 + wid * 16 + (lane >> 2);
    const uint32_t p1 = g_ptab4[F1], p2 = g_ptab4[F1 + 8];
    const float w1 = g_wtab[F1], w2 = g_wtab[F1 + 8];
    const uint32_t ao1 = p1 & 0xFFFFu, bo1 = p1 >> 16;
    const uint32_t ao2 = p2 & 0xFFFFu, bo2 = p2 >> 16;

    // init: kt cols 32..34 (both bufs); B rows 32 (ones hi) / 33 (zero), both bufs
    if (tid < 128) {
        float* r = (float*)(sm + (tid >> 6) * 64 * KSTR + (tid & 63) * KSTR);
        r[32] = 1.0f; r[33] = 0.0f; r[34] = 0.0f;
    }
    for (int i = tid; i < 2 * 2 * 2 * 36; i += 256) {      // buf, hi/lo, row32/33
        int b = i / 144, rem = i % 144;
        int reg = rem / 72, rr = 32 + (rem % 72) / 36, w = rem % 36;
        uint32_t val = (reg == 0 && rr == 32) ? 0x3C003C00u : 0u;   // fp16 1.0
        *(uint32_t*)(sm + OFF_B + b * BBUF + reg * BHALF + rr * BSTR + w * 4) = val;
    }

    // per-lane ldm4 row offsets: lanes 0-15 -> hi, 16-31 -> lo
    uint32_t rowoff[5];
#pragma unroll
    for (int nb = 0; nb < 5; ++nb) {
        int e = nb * 8 + (lane & 7);
        int er = e < 33 ? e : 33;
        rowoff[nb] = (uint32_t)((lane >= 16 ? BHALF : 0) + er * BSTR + ((lane >> 3) & 1) * 16);
    }

    float c[5][4] = {};
    const int c0b = (lane & 3) * 2;

    for (int cc = 0; cc < 16; ++cc) {
        const int buf = cc & 1;
        const int n0 = nh * 1024 + cc * 64;
        const uint32_t ktb = smb + buf * 64 * KSTR;
        const uint32_t bbB = smb + OFF_B + buf * BBUF;

        // stage k tile [64][32] fp32
        {
            int i2 = tid;
#pragma unroll
            for (int it = 0; it < 2; ++it, i2 += 256) {
                int rr = i2 >> 3, c4 = (i2 & 7) * 4;
                float4 t = *(const float4*)(kb + (size_t)(n0 + rr) * DD + c4);
                float* d = (float*)(sm + buf * 64 * KSTR + rr * KSTR) + c4;
                d[0] = t.x; d[1] = t.y; d[2] = t.z; d[3] = t.w;
            }
        }
        // build B rows 0..31 (Vaug^T, fp16 split)
#pragma unroll
        for (int it = 0; it < 4; ++it) {
            int i = it * 256 + tid;
            int np = i >> 5, e = i & 31;
            float v0 = vb[(size_t)(n0 + 2 * np) * DD + e];
            float v1 = vb[(size_t)(n0 + 2 * np) * DD + DD + e];
            uint32_t hp, lp; splitH2(v0, v1, hp, lp);
            *(uint32_t*)(sm + OFF_B + buf * BBUF + e * BSTR + np * 4) = hp;
            *(uint32_t*)(sm + OFF_B + buf * BBUF + BHALF + e * BSTR + np * 4) = lp;
        }
        __syncthreads();

#pragma unroll
        for (int ks = 0; ks < 4; ++ks) {
            const int c0 = ks * 16 + c0b;
            uint32_t ah[4], al[4];
            {
                const uint32_t pr0 = ktb + (uint32_t)(c0 * KSTR);
                const uint32_t pr1 = pr0 + KSTR;
                const uint32_t pr8 = pr0 + 8 * KSTR;
                const uint32_t pr9 = pr8 + KSTR;
                float x0, x1, y0, y1;
                asm("ld.shared.f32 %0, [%1];" : "=f"(x0) : "r"(pr0 + ao1));
                asm("ld.shared.f32 %0, [%1];" : "=f"(x1) : "r"(pr0 + bo1));
                asm("ld.shared.f32 %0, [%1];" : "=f"(y0) : "r"(pr1 + ao1));
                asm("ld.shared.f32 %0, [%1];" : "=f"(y1) : "r"(pr1 + bo1));
                splitH2(w1 * x0 * x1, w1 * y0 * y1, ah[0], al[0]);
                asm("ld.shared.f32 %0, [%1];" : "=f"(x0) : "r"(pr8 + ao1));
                asm("ld.shared.f32 %0, [%1];" : "=f"(x1) : "r"(pr8 + bo1));
                asm("ld.shared.f32 %0, [%1];" : "=f"(y0) : "r"(pr9 + ao1));
                asm("ld.shared.f32 %0, [%1];" : "=f"(y1) : "r"(pr9 + bo1));
                splitH2(w1 * x0 * x1, w1 * y0 * y1, ah[2], al[2]);
                asm("ld.shared.f32 %0, [%1];" : "=f"(x0) : "r"(pr0 + ao2));
                asm("ld.shared.f32 %0, [%1];" : "=f"(x1) : "r"(pr0 + bo2));
                asm("ld.shared.f32 %0, [%1];" : "=f"(y0) : "r"(pr1 + ao2));
                asm("ld.shared.f32 %0, [%1];" : "=f"(y1) : "r"(pr1 + bo2));
                splitH2(w2 * x0 * x1, w2 * y0 * y1, ah[1], al[1]);
                asm("ld.shared.f32 %0, [%1];" : "=f"(x0) : "r"(pr8 + ao2));
                asm("ld.shared.f32 %0, [%1];" : "=f"(x1) : "r"(pr8 + bo2));
                asm("ld.shared.f32 %0, [%1];" : "=f"(y0) : "r"(pr9 + ao2));
                asm("ld.shared.f32 %0, [%1];" : "=f"(y1) : "r"(pr9 + bo2));
                splitH2(w2 * x0 * x1, w2 * y0 * y1, ah[3], al[3]);
            }
#pragma unroll
            for (int nb = 0; nb < 5; ++nb) {
                uint32_t b4[4];
                ldm4(b4, bbB + rowoff[nb] + ks * 32);     // b4[0..1]=hi, b4[2..3]=lo
                mmaH(c[nb], ah, b4);
                mmaH(c[nb], ah, b4 + 2);
                mmaH(c[nb], al, b4);
            }
        }
    }

    // epilogue: 4 disjoint partial buffers, no atomics
    float* dst = g_M3p + (size_t)nh * (NBH * ER * FPAD) + (size_t)bh * ER * FPAD;
    const int Fg = F1;
#pragma unroll
    for (int nb = 0; nb < 5; ++nb) {
        const int e = nb * 8 + (lane & 3) * 2;
        if (nb < 4) {
            if (Fg < FTOT) {
                dst[(size_t)e * FPAD + Fg] = c[nb][0];
                dst[(size_t)(e + 1) * FPAD + Fg] = c[nb][1];
            }
            if (Fg + 8 < FTOT) {
                dst[(size_t)e * FPAD + Fg + 8] = c[nb][2];
                dst[(size_t)(e + 1) * FPAD + Fg + 8] = c[nb][3];
            }
        } else if ((lane & 3) == 0) {
            if (Fg < FTOT)     dst[(size_t)32 * FPAD + Fg] = c[4][0];
            if (Fg + 8 < FTOT) dst[(size_t)32 * FPAD + Fg + 8] = c[4][2];
        }
    }
}

// ---------------------------------------------------------------- combine+cvt
__global__ void cvtM3() {
    const size_t S = (size_t)NBH * ER * FPAD;
    size_t i = (size_t)blockIdx.x * 256 + threadIdx.x;
    int F = (int)(i % FPAD);
    float val = (F < FTOT)
        ? (g_M3p[i] + g_M3p[S + i] + g_M3p[2 * S + i] + g_M3p[3 * S + i]) : 0.0f;
    g_M3h[i] = __float2half_rn(val);
}

// ---------------------------------------------------------------- phase 2
// grid (NBH, 32 n-tiles). A = PhiQ single fp16 in registers; B = M3 single
// fp16; ONE mma + one ldm2 per (ks,nb); double-buffered; one sync per chunk.
__global__ __launch_bounds__(256, 4) void ph2(const float* __restrict__ q,
                                              float* __restrict__ out) {
    __shared__ __align__(16) char sm[128 * KSTR + 2560 + 2 * BHALF];  // 30272 B
    const int OFF_TAB = 128 * KSTR;            // 17920
    const int OFF_B = OFF_TAB + 2560;          // 20480
    const int bh = blockIdx.x, nt = blockIdx.y;
    const int tid = threadIdx.x, wid = tid >> 5, lane = tid & 31;
    const uint32_t smb = smem_u32(sm);

    // stage q tile [128][32] + cols 32..34 = {1,0,0}; copy table; zero row 33
    {
        const float4* qb4 = (const float4*)(q + ((size_t)bh * NSEQ + nt * 128) * DD);
        int i2 = tid;
#pragma unroll
        for (int it = 0; it < 4; ++it, i2 += 256) {
            int rr = i2 >> 3, c4 = (i2 & 7) * 4;
            float4 t = qb4[i2];
            float* d = (float*)(sm + rr * KSTR) + c4;
            d[0] = t.x; d[1] = t.y; d[2] = t.z; d[3] = t.w;
        }
        if (tid < 128) {
            float* r = (float*)(sm + tid * KSTR);
            r[32] = 1.0f; r[33] = 0.0f; r[34] = 0.0f;
        }
        for (int i = tid; i < 640; i += 256)
            *(uint32_t*)(sm + OFF_TAB + i * 4) = g_ptab4[i];
        for (int i = tid; i < 2 * 36; i += 256) {
            int b = i / 36, w = i % 36;
            *(uint32_t*)(sm + OFF_B + b * BHALF + 33 * BSTR + w * 4) = 0u;
        }
    }

    uint32_t rowoff[5];
#pragma unroll
    for (int nb = 0; nb < 5; ++nb) {
        int e = nb * 8 + (lane & 7);
        rowoff[nb] = (uint32_t)((e < 33 ? e : 33) * BSTR + ((lane >> 3) & 1) * 16);
    }

    const uint32_t q1 = smb + (uint32_t)((wid * 16 + (lane >> 2)) * KSTR);
    const uint32_t q2 = q1 + 8 * KSTR;
    const int c0b = (lane & 3) * 2;
    const __half* mh = g_M3h + (size_t)bh * ER * FPAD;

    float c[5][4] = {};

    for (int cc = 0; cc < 9; ++cc) {
        const int buf = cc & 1;
        const int f0 = cc * 64;
        const uint32_t bbB = smb + OFF_B + buf * BHALF;

        // build B rows 0..32 from M3 fp16 slice
        for (int i = tid; i < ER * 32; i += 256) {
            int e = i >> 5, j = i & 31;
            *(uint32_t*)(sm + OFF_B + buf * BHALF + e * BSTR + j * 4) =
                *(const uint32_t*)((const char*)(mh + (size_t)e * FPAD + f0) + j * 4);
        }
        __syncthreads();

#pragma unroll
        for (int ks = 0; ks < 4; ++ks) {
            const int c0 = f0 + ks * 16 + c0b;
            uint32_t a[4];
            {
                uint32_t t0, t1, t8, t9;
                asm("ld.shared.b32 %0, [%1];" : "=r"(t0) : "r"(smb + OFF_TAB + c0 * 4));
                asm("ld.shared.b32 %0, [%1];" : "=r"(t1) : "r"(smb + OFF_TAB + c0 * 4 + 4));
                asm("ld.shared.b32 %0, [%1];" : "=r"(t8) : "r"(smb + OFF_TAB + c0 * 4 + 32));
                asm("ld.shared.b32 %0, [%1];" : "=r"(t9) : "r"(smb + OFF_TAB + c0 * 4 + 36));
                float xa, xb, ya, yb;
                asm("ld.shared.f32 %0, [%1];" : "=f"(xa) : "r"(q1 + (t0 & 0xFFFFu)));
                asm("ld.shared.f32 %0, [%1];" : "=f"(xb) : "r"(q1 + (t0 >> 16)));
                asm("ld.shared.f32 %0, [%1];" : "=f"(ya) : "r"(q1 + (t1 & 0xFFFFu)));
                asm("ld.shared.f32 %0, [%1];" : "=f"(yb) : "r"(q1 + (t1 >> 16)));
                a[0] = packH2(xa * xb, ya * yb);
                asm("ld.shared.f32 %0, [%1];" : "=f"(xa) : "r"(q2 + (t0 & 0xFFFFu)));
                asm("ld.shared.f32 %0, [%1];" : "=f"(xb) : "r"(q2 + (t0 >> 16)));
                asm("ld.shared.f32 %0, [%1];" : "=f"(ya) : "r"(q2 + (t1 & 0xFFFFu)));
                asm("ld.shared.f32 %0, [%1];" : "=f"(yb) : "r"(q2 + (t1 >> 16)));
                a[1] = packH2(xa * xb, ya * yb);
                asm("ld.shared.f32 %0, [%1];" : "=f"(xa) : "r"(q1 + (t8 & 0xFFFFu)));
                asm("ld.shared.f32 %0, [%1];" : "=f"(xb) : "r"(q1 + (t8 >> 16)));
                asm("ld.shared.f32 %0, [%1];" : "=f"(ya) : "r"(q1 + (t9 & 0xFFFFu)));
                asm("ld.shared.f32 %0, [%1];" : "=f"(yb) : "r"(q1 + (t9 >> 16)));
                a[2] = packH2(xa * xb, ya * yb);
                asm("ld.shared.f32 %0, [%1];" : "=f"(xa) : "r"(q2 + (t8 & 0xFFFFu)));
                asm("ld.shared.f32 %0, [%1];" : "=f"(xb) : "r"(q2 + (t8 >> 16)));
                asm("ld.shared.f32 %0, [%1];" : "=f"(ya) : "r"(q2 + (t9 & 0xFFFFu)));
                asm("ld.shared.f32 %0, [%1];" : "=f"(yb) : "r"(q2 + (t9 >> 16)));
                a[3] = packH2(xa * xb, ya * yb);
            }
#pragma unroll
            for (int nb = 0; nb < 5; ++nb) {
                uint32_t b2[2];
                ldm2(b2, bbB + rowoff[nb] + ks * 32);
                mmaH(c[nb], a, b2);
            }
        }
    }

    // epilogue: divide by den (e=32 lives in nb=4, C col 0 -> lanes l%4==0)
    const float dl = __shfl_sync(0xFFFFFFFFu, c[4][0], lane & ~3);
    const float dh = __shfl_sync(0xFFFFFFFFu, c[4][2], lane & ~3);
    const float il = 1.0f / dl, ih = 1.0f / dh;
    const int row = nt * 128 + wid * 16 + (lane >> 2);
    float* ob = out + ((size_t)bh * NSEQ + row) * DD;
#pragma unroll
    for (int nb = 0; nb < 4; ++nb) {
        const int e = nb * 8 + (lane & 3) * 2;
        float2 lo2 = { c[nb][0] * il, c[nb][1] * il };
        float2 hi2 = { c[nb][2] * ih, c[nb][3] * ih };
        *(float2*)(ob + e) = lo2;
        *(float2*)(ob + 8 * DD + e) = hi2;
    }
}

// ---------------------------------------------------------------- launch
extern "C" void kernel_launch(void* const* d_in, const int* in_sizes, int n_in,
                              void* d_out, int out_size) {
    const float* q = (const float*)d_in[0];
    const float* k = (const float*)d_in[1];
    const float* v = (const float*)d_in[2];
    float* out = (float*)d_out;
    (void)in_sizes; (void)n_in; (void)out_size;

    initTab<<<3, 256>>>();
    ph1<<<dim3(NBH, 5, 4), 256>>>(k, v);
    cvtM3<<<(NBH * ER * FPAD) / 256, 256>>>();
    ph2<<<dim3(NBH, 32), 256>>>(q, out);
}

// round 7
// speedup vs baseline: 6.5401x; 1.0533x over previous
#include <cuda_runtime.h>
#include <cuda_fp16.h>
#include <cstdint>

// FAST attention (p=2 Taylor linear attention) as two unified feature GEMMs
// on HMMA fp16 (mma.sync m16n8k16, fp32 accum).
//   Phi[n,F]: F=0 -> 1, F=1..32 -> x_d, F=33..560 -> pair products
//   Phase 1: M3[F,e] = sum_n PhiK_w[n,F] * Vaug[n,e]
//            A single fp16, B hi/lo split -> 2 MMAs. M3 stored fp16.
//   Phase 2: D[n,e]  = sum_F PhiQ[n,F] * M3[F,e]; out = D[:,0:32]/D[:,32]
//            A single fp16, B single fp16 -> 1 MMA. 256-row tiles,
//            32 rows/warp (B fragments reused for 2 A-sets).

#define NBH   32
#define NSEQ  4096
#define DD    32
#define FTOT  561
#define FPAD  576
#define ER    33

#define KSTR  140          // staged fp32 tile row stride bytes (35 floats)
#define BSTR  144          // B row stride bytes (64 halves + pad)
#define BROWS 34           // 33 real + 1 zero row
#define BHALF (BROWS * BSTR)          // 4896
#define BBUF  (2 * BHALF)             // 9792 (hi + lo, ph1 only)

__device__ uint32_t g_ptab4[640];     // (a*4) | (b*4 << 16); pad -> col 33
__device__ float    g_wtab[640];      // ph1 row weight, pad 0
__device__ float    g_M3p[4 * NBH * ER * FPAD];     // 4 n-quarter partials
__device__ __half   g_M3h[NBH * ER * FPAD];

// ---------------------------------------------------------------- helpers
__device__ __forceinline__ uint32_t smem_u32(const void* p) {
    uint32_t a;
    asm("{ .reg .u64 t; cvta.to.shared.u64 t, %1; cvt.u32.u64 %0, t; }" : "=r"(a) : "l"(p));
    return a;
}
__device__ __forceinline__ uint32_t packH2(float v0, float v1) {
    uint32_t r;
    asm("cvt.rn.f16x2.f32 %0, %1, %2;" : "=r"(r) : "f"(v1), "f"(v0));  // lo=v0
    return r;
}
__device__ __forceinline__ void splitH2(float v0, float v1, uint32_t& hp, uint32_t& lp) {
    asm("cvt.rn.f16x2.f32 %0, %1, %2;" : "=r"(hp) : "f"(v1), "f"(v0));
    __half2 hh = *reinterpret_cast<__half2*>(&hp);
    float h0 = __low2float(hh), h1 = __high2float(hh);
    asm("cvt.rn.f16x2.f32 %0, %1, %2;" : "=r"(lp) : "f"(v1 - h1), "f"(v0 - h0));
}
__device__ __forceinline__ void ldm2(uint32_t b[2], uint32_t addr) {
    asm volatile("ldmatrix.sync.aligned.m8n8.x2.shared.b16 {%0,%1}, [%2];"
                 : "=r"(b[0]), "=r"(b[1]) : "r"(addr));
}
__device__ __forceinline__ void ldm4(uint32_t b[4], uint32_t addr) {
    asm volatile("ldmatrix.sync.aligned.m8n8.x4.shared.b16 {%0,%1,%2,%3}, [%4];"
                 : "=r"(b[0]), "=r"(b[1]), "=r"(b[2]), "=r"(b[3]) : "r"(addr));
}
__device__ __forceinline__ void mmaH(float c[4], const uint32_t a[4], const uint32_t b[2]) {
    asm volatile("mma.sync.aligned.m16n8k16.row.col.f32.f16.f16.f32 "
                 "{%0,%1,%2,%3}, {%4,%5,%6,%7}, {%8,%9}, {%0,%1,%2,%3};"
                 : "+f"(c[0]), "+f"(c[1]), "+f"(c[2]), "+f"(c[3])
                 : "r"(a[0]), "r"(a[1]), "r"(a[2]), "r"(a[3]), "r"(b[0]), "r"(b[1]));
}
// product of two staged fp32 values at row base `pr` with byte offsets ao, bo
__device__ __forceinline__ float prod2(uint32_t pr, uint32_t ao, uint32_t bo) {
    float x, y;
    asm("ld.shared.f32 %0, [%1];" : "=f"(x) : "r"(pr + ao));
    asm("ld.shared.f32 %0, [%1];" : "=f"(y) : "r"(pr + bo));
    return x * y;
}
// A fragment from packed col tables ta (col c), tb (col c+1) at q-row base
__device__ __forceinline__ uint32_t afrag(uint32_t qr, uint32_t ta, uint32_t tb) {
    float v0 = prod2(qr, ta & 0xFFFFu, ta >> 16);
    float v1 = prod2(qr, tb & 0xFFFFu, tb >> 16);
    return packH2(v0, v1);
}

// ---------------------------------------------------------------- init table
__global__ void initTab() {
    int F = blockIdx.x * 256 + threadIdx.x;
    if (F >= 640) return;
    int a = 33, b = 33;
    float w = 0.0f;
    if (F == 0) { a = 32; b = 32; w = 1.0f; }
    else if (F < 33) { a = F - 1; b = 32; w = 1.0f; }
    else if (F < FTOT) {
        int p = F - 33, f1 = 0;
        while (p >= 32 - f1) { p -= 32 - f1; ++f1; }
        a = f1; b = f1 + p;
        w = (a == b) ? 0.5f : 1.0f;
    }
    g_ptab4[F] = (uint32_t)(a * 4) | ((uint32_t)(b * 4) << 16);
    g_wtab[F] = w;
}

// ---------------------------------------------------------------- phase 1
// grid (NBH, 5 F-tiles, 4 n-quarters). A (PhiK_w) single fp16 in registers;
// B = Vaug^T fp16 hi/lo; 2 MMAs; double-buffered; one sync per chunk.
__global__ __launch_bounds__(256, 4) void ph1(const float* __restrict__ k,
                                              const float* __restrict__ v) {
    __shared__ __align__(16) char sm[2 * 64 * KSTR + 2 * BBUF];   // 37504 B
    const int OFF_B = 2 * 64 * KSTR;                               // 17920
    const int bh = blockIdx.x, ft = blockIdx.y, nh = blockIdx.z;
    const int tid = threadIdx.x, wid = tid >> 5, lane = tid & 31;
    const uint32_t smb = smem_u32(sm);

    const float* kb = k + (size_t)bh * NSEQ * DD;
    const float* vb = v + (size_t)bh * NSEQ * DD;

    const int F1 = ft * 128 + wid * 16 + (lane >> 2);
    const uint32_t p1 = g_ptab4[F1], p2 = g_ptab4[F1 + 8];
    const float w1 = g_wtab[F1], w2 = g_wtab[F1 + 8];
    const uint32_t ao1 = p1 & 0xFFFFu, bo1 = p1 >> 16;
    const uint32_t ao2 = p2 & 0xFFFFu, bo2 = p2 >> 16;

    // init: kt cols 32..34 (both bufs); B rows 32 (ones hi) / 33 (zero), both bufs
    if (tid < 128) {
        float* r = (float*)(sm + (tid >> 6) * 64 * KSTR + (tid & 63) * KSTR);
        r[32] = 1.0f; r[33] = 0.0f; r[34] = 0.0f;
    }
    for (int i = tid; i < 2 * 2 * 2 * 36; i += 256) {      // buf, hi/lo, row32/33
        int b = i / 144, rem = i % 144;
        int reg = rem / 72, rr = 32 + (rem % 72) / 36, w = rem % 36;
        uint32_t val = (reg == 0 && rr == 32) ? 0x3C003C00u : 0u;   // fp16 1.0
        *(uint32_t*)(sm + OFF_B + b * BBUF + reg * BHALF + rr * BSTR + w * 4) = val;
    }

    // per-lane ldm4 row offsets: lanes 0-15 -> hi, 16-31 -> lo
    uint32_t rowoff[5];
#pragma unroll
    for (int nb = 0; nb < 5; ++nb) {
        int e = nb * 8 + (lane & 7);
        int er = e < 33 ? e : 33;
        rowoff[nb] = (uint32_t)((lane >= 16 ? BHALF : 0) + er * BSTR + ((lane >> 3) & 1) * 16);
    }

    float c[5][4] = {};
    const int c0b = (lane & 3) * 2;

    for (int cc = 0; cc < 16; ++cc) {
        const int buf = cc & 1;
        const int n0 = nh * 1024 + cc * 64;
        const uint32_t ktb = smb + buf * 64 * KSTR;
        const uint32_t bbB = smb + OFF_B + buf * BBUF;

        // stage k tile [64][32] fp32
        {
            int i2 = tid;
#pragma unroll
            for (int it = 0; it < 2; ++it, i2 += 256) {
                int rr = i2 >> 3, c4 = (i2 & 7) * 4;
                float4 t = *(const float4*)(kb + (size_t)(n0 + rr) * DD + c4);
                float* d = (float*)(sm + buf * 64 * KSTR + rr * KSTR) + c4;
                d[0] = t.x; d[1] = t.y; d[2] = t.z; d[3] = t.w;
            }
        }
        // build B rows 0..31 (Vaug^T, fp16 split)
#pragma unroll
        for (int it = 0; it < 4; ++it) {
            int i = it * 256 + tid;
            int np = i >> 5, e = i & 31;
            float v0 = vb[(size_t)(n0 + 2 * np) * DD + e];
            float v1 = vb[(size_t)(n0 + 2 * np) * DD + DD + e];
            uint32_t hp, lp; splitH2(v0, v1, hp, lp);
            *(uint32_t*)(sm + OFF_B + buf * BBUF + e * BSTR + np * 4) = hp;
            *(uint32_t*)(sm + OFF_B + buf * BBUF + BHALF + e * BSTR + np * 4) = lp;
        }
        __syncthreads();

#pragma unroll
        for (int ks = 0; ks < 4; ++ks) {
            const int c0 = ks * 16 + c0b;
            uint32_t ah[4];
            {
                const uint32_t pr0 = ktb + (uint32_t)(c0 * KSTR);
                const uint32_t pr1 = pr0 + KSTR;
                const uint32_t pr8 = pr0 + 8 * KSTR;
                const uint32_t pr9 = pr8 + KSTR;
                ah[0] = packH2(w1 * prod2(pr0, ao1, bo1), w1 * prod2(pr1, ao1, bo1));
                ah[2] = packH2(w1 * prod2(pr8, ao1, bo1), w1 * prod2(pr9, ao1, bo1));
                ah[1] = packH2(w2 * prod2(pr0, ao2, bo2), w2 * prod2(pr1, ao2, bo2));
                ah[3] = packH2(w2 * prod2(pr8, ao2, bo2), w2 * prod2(pr9, ao2, bo2));
            }
#pragma unroll
            for (int nb = 0; nb < 5; ++nb) {
                uint32_t b4[4];
                ldm4(b4, bbB + rowoff[nb] + ks * 32);     // b4[0..1]=hi, b4[2..3]=lo
                mmaH(c[nb], ah, b4);
                mmaH(c[nb], ah, b4 + 2);
            }
        }
    }

    // epilogue: 4 disjoint partial buffers, no atomics
    float* dst = g_M3p + (size_t)nh * (NBH * ER * FPAD) + (size_t)bh * ER * FPAD;
    const int Fg = F1;
#pragma unroll
    for (int nb = 0; nb < 5; ++nb) {
        const int e = nb * 8 + (lane & 3) * 2;
        if (nb < 4) {
            if (Fg < FTOT) {
                dst[(size_t)e * FPAD + Fg] = c[nb][0];
                dst[(size_t)(e + 1) * FPAD + Fg] = c[nb][1];
            }
            if (Fg + 8 < FTOT) {
                dst[(size_t)e * FPAD + Fg + 8] = c[nb][2];
                dst[(size_t)(e + 1) * FPAD + Fg + 8] = c[nb][3];
            }
        } else if ((lane & 3) == 0) {
            if (Fg < FTOT)     dst[(size_t)32 * FPAD + Fg] = c[4][0];
            if (Fg + 8 < FTOT) dst[(size_t)32 * FPAD + Fg + 8] = c[4][2];
        }
    }
}

// ---------------------------------------------------------------- combine+cvt
__global__ void cvtM3() {
    const size_t S = (size_t)NBH * ER * FPAD;
    size_t i = (size_t)blockIdx.x * 256 + threadIdx.x;
    int F = (int)(i % FPAD);
    float val = (F < FTOT)
        ? (g_M3p[i] + g_M3p[S + i] + g_M3p[2 * S + i] + g_M3p[3 * S + i]) : 0.0f;
    g_M3h[i] = __float2half_rn(val);
}

// ---------------------------------------------------------------- phase 2
// grid (NBH, 16 n-tiles of 256 rows). 8 warps x 32 rows: two A sets per warp
// share each B fragment (halves B ldmatrix traffic per row). 1 MMA each.
__global__ __launch_bounds__(256, 3) void ph2(const float* __restrict__ q,
                                              float* __restrict__ out) {
    __shared__ __align__(16) char sm[256 * KSTR + 2560 + 2 * BHALF];  // 48192 B
    const int OFF_TAB = 256 * KSTR;            // 35840
    const int OFF_B = OFF_TAB + 2560;          // 38400
    const int bh = blockIdx.x, nt = blockIdx.y;
    const int tid = threadIdx.x, wid = tid >> 5, lane = tid & 31;
    const uint32_t smb = smem_u32(sm);

    // stage q tile [256][32] + cols 32..34 = {1,0,0}; copy table; zero row 33
    {
        const float4* qb4 = (const float4*)(q + ((size_t)bh * NSEQ + nt * 256) * DD);
        int i2 = tid;
#pragma unroll
        for (int it = 0; it < 8; ++it, i2 += 256) {
            int rr = i2 >> 3, c4 = (i2 & 7) * 4;
            float4 t = qb4[i2];
            float* d = (float*)(sm + rr * KSTR) + c4;
            d[0] = t.x; d[1] = t.y; d[2] = t.z; d[3] = t.w;
        }
        {
            float* r = (float*)(sm + tid * KSTR);
            r[32] = 1.0f; r[33] = 0.0f; r[34] = 0.0f;
        }
        for (int i = tid; i < 640; i += 256)
            *(uint32_t*)(sm + OFF_TAB + i * 4) = g_ptab4[i];
        for (int i = tid; i < 2 * 36; i += 256) {
            int b = i / 36, w = i % 36;
            *(uint32_t*)(sm + OFF_B + b * BHALF + 33 * BSTR + w * 4) = 0u;
        }
    }

    // B fragment offsets: two ldm4 nb-pairs (nb0/1, nb2/3) + ldm2 for nb4
    uint32_t rowp[2];
#pragma unroll
    for (int p = 0; p < 2; ++p) {
        int m = lane >> 3;
        int nb = p * 2 + (m >> 1);
        int e = nb * 8 + (lane & 7);              // <= 31, no clamp needed
        rowp[p] = (uint32_t)(e * BSTR + (m & 1) * 16);
    }
    uint32_t rowoff4;
    {
        int e = 32 + (lane & 7);
        rowoff4 = (uint32_t)((e < 33 ? e : 33) * BSTR + ((lane >> 3) & 1) * 16);
    }

    const uint32_t qb_ = smb + (uint32_t)((wid * 32 + (lane >> 2)) * KSTR);
    const uint32_t q1 = qb_, q2 = qb_ + 8 * KSTR;
    const uint32_t q3 = qb_ + 16 * KSTR, q4 = qb_ + 24 * KSTR;
    const int c0b = (lane & 3) * 2;
    const __half* mh = g_M3h + (size_t)bh * ER * FPAD;

    float c[2][5][4] = {};

    for (int cc = 0; cc < 9; ++cc) {
        const int buf = cc & 1;
        const int f0 = cc * 64;
        const uint32_t bbB = smb + OFF_B + buf * BHALF;

        // build B rows 0..32 from M3 fp16 slice
        for (int i = tid; i < ER * 32; i += 256) {
            int e = i >> 5, j = i & 31;
            *(uint32_t*)(sm + OFF_B + buf * BHALF + e * BSTR + j * 4) =
                *(const uint32_t*)((const char*)(mh + (size_t)e * FPAD + f0) + j * 4);
        }
        __syncthreads();

#pragma unroll
        for (int ks = 0; ks < 4; ++ks) {
            const int c0 = f0 + ks * 16 + c0b;
            uint32_t t0, t1, t8, t9;
            asm("ld.shared.b32 %0, [%1];" : "=r"(t0) : "r"(smb + OFF_TAB + c0 * 4));
            asm("ld.shared.b32 %0, [%1];" : "=r"(t1) : "r"(smb + OFF_TAB + c0 * 4 + 4));
            asm("ld.shared.b32 %0, [%1];" : "=r"(t8) : "r"(smb + OFF_TAB + c0 * 4 + 32));
            asm("ld.shared.b32 %0, [%1];" : "=r"(t9) : "r"(smb + OFF_TAB + c0 * 4 + 36));
            uint32_t a0[4], a1[4];
            a0[0] = afrag(q1, t0, t1); a0[1] = afrag(q2, t0, t1);
            a0[2] = afrag(q1, t8, t9); a0[3] = afrag(q2, t8, t9);
            a1[0] = afrag(q3, t0, t1); a1[1] = afrag(q4, t0, t1);
            a1[2] = afrag(q3, t8, t9); a1[3] = afrag(q4, t8, t9);

            uint32_t b01[4], b23[4], b4[2];
            ldm4(b01, bbB + rowp[0] + ks * 32);
            ldm4(b23, bbB + rowp[1] + ks * 32);
            ldm2(b4, bbB + rowoff4 + ks * 32);
            mmaH(c[0][0], a0, b01);     mmaH(c[1][0], a1, b01);
            mmaH(c[0][1], a0, b01 + 2); mmaH(c[1][1], a1, b01 + 2);
            mmaH(c[0][2], a0, b23);     mmaH(c[1][2], a1, b23);
            mmaH(c[0][3], a0, b23 + 2); mmaH(c[1][3], a1, b23 + 2);
            mmaH(c[0][4], a0, b4);      mmaH(c[1][4], a1, b4);
        }
    }

    // epilogue per A-set: divide by den (e=32 -> nb4 col 0, lanes l%4==0)
#pragma unroll
    for (int s = 0; s < 2; ++s) {
        const float dl = __shfl_sync(0xFFFFFFFFu, c[s][4][0], lane & ~3);
        const float dh = __shfl_sync(0xFFFFFFFFu, c[s][4][2], lane & ~3);
        const float il = 1.0f / dl, ih = 1.0f / dh;
        const int row = nt * 256 + wid * 32 + s * 16 + (lane >> 2);
        float* ob = out + ((size_t)bh * NSEQ + row) * DD;
#pragma unroll
        for (int nb = 0; nb < 4; ++nb) {
            const int e = nb * 8 + (lane & 3) * 2;
            float2 lo2 = { c[s][nb][0] * il, c[s][nb][1] * il };
            float2 hi2 = { c[s][nb][2] * ih, c[s][nb][3] * ih };
            *(float2*)(ob + e) = lo2;
            *(float2*)(ob + 8 * DD + e) = hi2;
        }
    }
}

// ---------------------------------------------------------------- launch
extern "C" void kernel_launch(void* const* d_in, const int* in_sizes, int n_in,
                              void* d_out, int out_size) {
    const float* q = (const float*)d_in[0];
    const float* k = (const float*)d_in[1];
    const float* v = (const float*)d_in[2];
    float* out = (float*)d_out;
    (void)in_sizes; (void)n_in; (void)out_size;

    initTab<<<3, 256>>>();
    ph1<<<dim3(NBH, 5, 4), 256>>>(k, v);
    cvtM3<<<(NBH * ER * FPAD) / 256, 256>>>();
    ph2<<<dim3(NBH, 16), 256>>>(q, out);
}

// round 8
// speedup vs baseline: 7.9997x; 1.2232x over previous
#include <cuda_runtime.h>
#include <cuda_fp16.h>
#include <cstdint>

// FAST attention (p=2 Taylor linear attention) as two unified feature GEMMs
// on HMMA fp16 (mma.sync m16n8k16, fp32 accum).
//   Phi[n,F]: F=0 -> 1, F=1..32 -> x_d, F=33..560 -> pair products
//   Phase 1: M3[F,e] = sum_n PhiK_w[n,F] * Vaug[n,e]   (all-fp16 operands)
//   cvt:     combine 8 n-partials, emit M3 as pre-swizzled mma B-fragments
//   Phase 2: D[n,e]  = sum_F PhiQ[n,F] * M3[F,e]; out = D[:,0:32]/D[:,32]
//            B loaded per-lane from gmem fragments: no smem B, no syncs.

#define NBH   32
#define NSEQ  4096
#define DD    32
#define FTOT  561
#define FPAD  576
#define ER    33
#define NPART 8

#define KSTR  140          // staged fp32 tile row stride bytes (35 floats)
#define BSTR  144          // ph1 B row stride bytes (64 halves + pad)
#define BROWS 34           // 33 real + 1 zero row
#define BHALF (BROWS * BSTR)          // 4896

__device__ uint32_t g_ptab4[640];     // (a*4) | (b*4 << 16); pad -> col 33
__device__ float    g_wtab[640];      // ph1 row weight, pad 0
__device__ float    g_M3p[NPART * NBH * ER * FPAD];
__device__ uint2    g_M3frag[NBH * 36 * 5 * 32];   // [bh][ks][nb][lane]

// ---------------------------------------------------------------- helpers
__device__ __forceinline__ uint32_t smem_u32(const void* p) {
    uint32_t a;
    asm("{ .reg .u64 t; cvta.to.shared.u64 t, %1; cvt.u32.u64 %0, t; }" : "=r"(a) : "l"(p));
    return a;
}
__device__ __forceinline__ uint32_t packH2(float v0, float v1) {
    uint32_t r;
    asm("cvt.rn.f16x2.f32 %0, %1, %2;" : "=r"(r) : "f"(v1), "f"(v0));  // lo=v0
    return r;
}
__device__ __forceinline__ void ldm2(uint32_t b[2], uint32_t addr) {
    asm volatile("ldmatrix.sync.aligned.m8n8.x2.shared.b16 {%0,%1}, [%2];"
                 : "=r"(b[0]), "=r"(b[1]) : "r"(addr));
}
__device__ __forceinline__ void ldm4(uint32_t b[4], uint32_t addr) {
    asm volatile("ldmatrix.sync.aligned.m8n8.x4.shared.b16 {%0,%1,%2,%3}, [%4];"
                 : "=r"(b[0]), "=r"(b[1]), "=r"(b[2]), "=r"(b[3]) : "r"(addr));
}
__device__ __forceinline__ void mmaH(float c[4], const uint32_t a[4], const uint32_t b[2]) {
    asm volatile("mma.sync.aligned.m16n8k16.row.col.f32.f16.f16.f32 "
                 "{%0,%1,%2,%3}, {%4,%5,%6,%7}, {%8,%9}, {%0,%1,%2,%3};"
                 : "+f"(c[0]), "+f"(c[1]), "+f"(c[2]), "+f"(c[3])
                 : "r"(a[0]), "r"(a[1]), "r"(a[2]), "r"(a[3]), "r"(b[0]), "r"(b[1]));
}
__device__ __forceinline__ float prod2(uint32_t pr, uint32_t ao, uint32_t bo) {
    float x, y;
    asm("ld.shared.f32 %0, [%1];" : "=f"(x) : "r"(pr + ao));
    asm("ld.shared.f32 %0, [%1];" : "=f"(y) : "r"(pr + bo));
    return x * y;
}
__device__ __forceinline__ uint32_t afrag(uint32_t qr, uint32_t ta, uint32_t tb) {
    float v0 = prod2(qr, ta & 0xFFFFu, ta >> 16);
    float v1 = prod2(qr, tb & 0xFFFFu, tb >> 16);
    return packH2(v0, v1);
}

// ---------------------------------------------------------------- init table
__global__ void initTab() {
    int F = blockIdx.x * 256 + threadIdx.x;
    if (F >= 640) return;
    int a = 33, b = 33;
    float w = 0.0f;
    if (F == 0) { a = 32; b = 32; w = 1.0f; }
    else if (F < 33) { a = F - 1; b = 32; w = 1.0f; }
    else if (F < FTOT) {
        int p = F - 33, f1 = 0;
        while (p >= 32 - f1) { p -= 32 - f1; ++f1; }
        a = f1; b = f1 + p;
        w = (a == b) ? 0.5f : 1.0f;
    }
    g_ptab4[F] = (uint32_t)(a * 4) | ((uint32_t)(b * 4) << 16);
    g_wtab[F] = w;
}

// ---------------------------------------------------------------- phase 1
// grid (NBH, 5 F-tiles, NPART n-slices). A (PhiK_w) single fp16 in regs;
// B = Vaug^T single fp16; 1 MMA per (ks,nb); double-buffered; 1 sync/chunk.
__global__ __launch_bounds__(256, 4) void ph1(const float* __restrict__ k,
                                              const float* __restrict__ v) {
    __shared__ __align__(16) char sm[2 * 64 * KSTR + 2 * BHALF];   // 27712 B
    const int OFF_B = 2 * 64 * KSTR;                               // 17920
    const int bh = blockIdx.x, ft = blockIdx.y, nh = blockIdx.z;
    const int tid = threadIdx.x, wid = tid >> 5, lane = tid & 31;
    const uint32_t smb = smem_u32(sm);

    const float* kb = k + (size_t)bh * NSEQ * DD;
    const float* vb = v + (size_t)bh * NSEQ * DD;

    const int F1 = ft * 128 + wid * 16 + (lane >> 2);
    const uint32_t p1 = g_ptab4[F1], p2 = g_ptab4[F1 + 8];
    const float w1 = g_wtab[F1], w2 = g_wtab[F1 + 8];
    const uint32_t ao1 = p1 & 0xFFFFu, bo1 = p1 >> 16;
    const uint32_t ao2 = p2 & 0xFFFFu, bo2 = p2 >> 16;

    // init: kt cols 32..34 (both bufs); B rows 32 (ones) / 33 (zero), both bufs
    if (tid < 128) {
        float* r = (float*)(sm + (tid >> 6) * 64 * KSTR + (tid & 63) * KSTR);
        r[32] = 1.0f; r[33] = 0.0f; r[34] = 0.0f;
    }
    for (int i = tid; i < 2 * 2 * 36; i += 256) {          // buf, row32/33
        int b = i / 72, rr = 32 + (i % 72) / 36, w = i % 36;
        uint32_t val = (rr == 32) ? 0x3C003C00u : 0u;       // fp16 1.0 pair
        *(uint32_t*)(sm + OFF_B + b * BHALF + rr * BSTR + w * 4) = val;
    }

    // B fragment offsets: ldm4 pairs (nb0/1, nb2/3) + ldm2 nb4 (clamped)
    uint32_t rowp[2];
#pragma unroll
    for (int p = 0; p < 2; ++p) {
        int m = lane >> 3;
        int nb = p * 2 + (m >> 1);
        int e = nb * 8 + (lane & 7);
        rowp[p] = (uint32_t)(e * BSTR + (m & 1) * 16);
    }
    uint32_t rowoff4;
    {
        int e = 32 + (lane & 7);
        rowoff4 = (uint32_t)((e < 33 ? e : 33) * BSTR + ((lane >> 3) & 1) * 16);
    }

    float c[5][4] = {};
    const int c0b = (lane & 3) * 2;
    const int NC = (NSEQ / NPART) / 64;                     // chunks per block

    for (int cc = 0; cc < NC; ++cc) {
        const int buf = cc & 1;
        const int n0 = nh * (NSEQ / NPART) + cc * 64;
        const uint32_t ktb = smb + buf * 64 * KSTR;
        const uint32_t bbB = smb + OFF_B + buf * BHALF;

        // stage k tile [64][32] fp32
        {
            int i2 = tid;
#pragma unroll
            for (int it = 0; it < 2; ++it, i2 += 256) {
                int rr = i2 >> 3, c4 = (i2 & 7) * 4;
                float4 t = *(const float4*)(kb + (size_t)(n0 + rr) * DD + c4);
                float* d = (float*)(sm + buf * 64 * KSTR + rr * KSTR) + c4;
                d[0] = t.x; d[1] = t.y; d[2] = t.z; d[3] = t.w;
            }
        }
        // build B rows 0..31 (Vaug^T, single fp16)
#pragma unroll
        for (int it = 0; it < 4; ++it) {
            int i = it * 256 + tid;
            int np = i >> 5, e = i & 31;
            float v0 = vb[(size_t)(n0 + 2 * np) * DD + e];
            float v1 = vb[(size_t)(n0 + 2 * np) * DD + DD + e];
            *(uint32_t*)(sm + OFF_B + buf * BHALF + e * BSTR + np * 4) = packH2(v0, v1);
        }
        __syncthreads();

#pragma unroll
        for (int ks = 0; ks < 4; ++ks) {
            const int c0 = ks * 16 + c0b;
            uint32_t ah[4];
            {
                const uint32_t pr0 = ktb + (uint32_t)(c0 * KSTR);
                const uint32_t pr1 = pr0 + KSTR;
                const uint32_t pr8 = pr0 + 8 * KSTR;
                const uint32_t pr9 = pr8 + KSTR;
                ah[0] = packH2(w1 * prod2(pr0, ao1, bo1), w1 * prod2(pr1, ao1, bo1));
                ah[2] = packH2(w1 * prod2(pr8, ao1, bo1), w1 * prod2(pr9, ao1, bo1));
                ah[1] = packH2(w2 * prod2(pr0, ao2, bo2), w2 * prod2(pr1, ao2, bo2));
                ah[3] = packH2(w2 * prod2(pr8, ao2, bo2), w2 * prod2(pr9, ao2, bo2));
            }
            uint32_t b01[4], b23[4], b4[2];
            ldm4(b01, bbB + rowp[0] + ks * 32);
            ldm4(b23, bbB + rowp[1] + ks * 32);
            ldm2(b4, bbB + rowoff4 + ks * 32);
            mmaH(c[0], ah, b01);
            mmaH(c[1], ah, b01 + 2);
            mmaH(c[2], ah, b23);
            mmaH(c[3], ah, b23 + 2);
            mmaH(c[4], ah, b4);
        }
    }

    // epilogue: NPART disjoint partial buffers, no atomics
    float* dst = g_M3p + (size_t)nh * (NBH * ER * FPAD) + (size_t)bh * ER * FPAD;
    const int Fg = F1;
#pragma unroll
    for (int nb = 0; nb < 5; ++nb) {
        const int e = nb * 8 + (lane & 3) * 2;
        if (nb < 4) {
            if (Fg < FTOT) {
                dst[(size_t)e * FPAD + Fg] = c[nb][0];
                dst[(size_t)(e + 1) * FPAD + Fg] = c[nb][1];
            }
            if (Fg + 8 < FTOT) {
                dst[(size_t)e * FPAD + Fg + 8] = c[nb][2];
                dst[(size_t)(e + 1) * FPAD + Fg + 8] = c[nb][3];
            }
        } else if ((lane & 3) == 0) {
            if (Fg < FTOT)     dst[(size_t)32 * FPAD + Fg] = c[4][0];
            if (Fg + 8 < FTOT) dst[(size_t)32 * FPAD + Fg + 8] = c[4][2];
        }
    }
}

// ---------------------------------------------------------------- combine+cvt
// Combine NPART partials; emit fp16 B-fragments in the exact per-lane order
// mma.m16n8k16 needs: word(bh,ks,nb,lane) = { (M3[e][F0],M3[e][F0+1]),
// (M3[e][F0+8],M3[e][F0+9]) }, e = nb*8+lane/4, F0 = ks*16+2*(lane%4).
__global__ void cvtM3() {
    const size_t S = (size_t)NBH * ER * FPAD;
    int i = blockIdx.x * 256 + threadIdx.x;                // < 184320
    int lane = i & 31;
    int nb = (i >> 5) % 5;
    int ks = (i / 160) % 36;
    int bh = i / 5760;
    int e = nb * 8 + (lane >> 2);
    int F0 = ks * 16 + 2 * (lane & 3);
    float vals[4];
    const int Fs[4] = {F0, F0 + 1, F0 + 8, F0 + 9};
#pragma unroll
    for (int t = 0; t < 4; ++t) {
        float s = 0.0f;
        if (e <= 32 && Fs[t] < FTOT) {
            size_t off = (size_t)(bh * ER + e) * FPAD + Fs[t];
#pragma unroll
            for (int p = 0; p < NPART; ++p) s += g_M3p[p * S + off];
        }
        vals[t] = s;
    }
    uint2 w;
    w.x = packH2(vals[0], vals[1]);
    w.y = packH2(vals[2], vals[3]);
    g_M3frag[i] = w;
}

// ---------------------------------------------------------------- phase 2
// grid (NBH, 16 n-tiles of 256 rows). 8 warps x 32 rows (2 A-sets). B comes
// per-lane from g_M3frag via coalesced LDG.64 — no B smem, no mainloop syncs.
__global__ __launch_bounds__(256, 4) void ph2(const float* __restrict__ q,
                                              float* __restrict__ out) {
    __shared__ __align__(16) char sm[256 * KSTR + 2560];   // 38400 B
    const int OFF_TAB = 256 * KSTR;                        // 35840
    const int bh = blockIdx.x, nt = blockIdx.y;
    const int tid = threadIdx.x, wid = tid >> 5, lane = tid & 31;
    const uint32_t smb = smem_u32(sm);

    // stage q tile [256][32] + cols 32..34 = {1,0,0}; copy table
    {
        const float4* qb4 = (const float4*)(q + ((size_t)bh * NSEQ + nt * 256) * DD);
        int i2 = tid;
#pragma unroll
        for (int it = 0; it < 8; ++it, i2 += 256) {
            int rr = i2 >> 3, c4 = (i2 & 7) * 4;
            float4 t = qb4[i2];
            float* d = (float*)(sm + rr * KSTR) + c4;
            d[0] = t.x; d[1] = t.y; d[2] = t.z; d[3] = t.w;
        }
        {
            float* r = (float*)(sm + tid * KSTR);
            r[32] = 1.0f; r[33] = 0.0f; r[34] = 0.0f;
        }
        for (int i = tid; i < 640; i += 256)
            *(uint32_t*)(sm + OFF_TAB + i * 4) = g_ptab4[i];
    }
    __syncthreads();

    const uint32_t q1 = smb + (uint32_t)((wid * 32 + (lane >> 2)) * KSTR);
    const int c0b = (lane & 3) * 2;
    const uint2* frag = g_M3frag + (size_t)bh * (36 * 5 * 32) + lane;

    float c[2][5][4] = {};

    for (int ks = 0; ks < 36; ++ks) {
        // B fragments straight from gmem (L2-resident), fully coalesced
        const uint2* fb = frag + ks * (5 * 32);
        uint2 b0 = __ldg(fb);
        uint2 b1 = __ldg(fb + 32);
        uint2 b2 = __ldg(fb + 64);
        uint2 b3 = __ldg(fb + 96);
        uint2 b4 = __ldg(fb + 128);

        const int c0 = ks * 16 + c0b;
        uint32_t t0, t1, t8, t9;
        asm("ld.shared.b32 %0, [%1];" : "=r"(t0) : "r"(smb + OFF_TAB + c0 * 4));
        asm("ld.shared.b32 %0, [%1];" : "=r"(t1) : "r"(smb + OFF_TAB + c0 * 4 + 4));
        asm("ld.shared.b32 %0, [%1];" : "=r"(t8) : "r"(smb + OFF_TAB + c0 * 4 + 32));
        asm("ld.shared.b32 %0, [%1];" : "=r"(t9) : "r"(smb + OFF_TAB + c0 * 4 + 36));

        uint32_t a0[4], a1[4];
        a0[0] = afrag(q1, t0, t1);
        a0[1] = afrag(q1 + 8 * KSTR, t0, t1);
        a0[2] = afrag(q1, t8, t9);
        a0[3] = afrag(q1 + 8 * KSTR, t8, t9);
        a1[0] = afrag(q1 + 16 * KSTR, t0, t1);
        a1[1] = afrag(q1 + 24 * KSTR, t0, t1);
        a1[2] = afrag(q1 + 16 * KSTR, t8, t9);
        a1[3] = afrag(q1 + 24 * KSTR, t8, t9);

        mmaH(c[0][0], a0, (const uint32_t*)&b0);
        mmaH(c[1][0], a1, (const uint32_t*)&b0);
        mmaH(c[0][1], a0, (const uint32_t*)&b1);
        mmaH(c[1][1], a1, (const uint32_t*)&b1);
        mmaH(c[0][2], a0, (const uint32_t*)&b2);
        mmaH(c[1][2], a1, (const uint32_t*)&b2);
        mmaH(c[0][3], a0, (const uint32_t*)&b3);
        mmaH(c[1][3], a1, (const uint32_t*)&b3);
        mmaH(c[0][4], a0, (const uint32_t*)&b4);
        mmaH(c[1][4], a1, (const uint32_t*)&b4);
    }

    // epilogue per A-set: divide by den (e=32 -> nb4 col 0, lanes l%4==0)
#pragma unroll
    for (int s = 0; s < 2; ++s) {
        const float dl = __shfl_sync(0xFFFFFFFFu, c[s][4][0], lane & ~3);
        const float dh = __shfl_sync(0xFFFFFFFFu, c[s][4][2], lane & ~3);
        const float il = 1.0f / dl, ih = 1.0f / dh;
        const int row = nt * 256 + wid * 32 + s * 16 + (lane >> 2);
        float* ob = out + ((size_t)bh * NSEQ + row) * DD;
#pragma unroll
        for (int nb = 0; nb < 4; ++nb) {
            const int e = nb * 8 + (lane & 3) * 2;
            float2 lo2 = { c[s][nb][0] * il, c[s][nb][1] * il };
            float2 hi2 = { c[s][nb][2] * ih, c[s][nb][3] * ih };
            *(float2*)(ob + e) = lo2;
            *(float2*)(ob + 8 * DD + e) = hi2;
        }
    }
}

// ---------------------------------------------------------------- launch
extern "C" void kernel_launch(void* const* d_in, const int* in_sizes, int n_in,
                              void* d_out, int out_size) {
    const float* q = (const float*)d_in[0];
    const float* k = (const float*)d_in[1];
    const float* v = (const float*)d_in[2];
    float* out = (float*)d_out;
    (void)in_sizes; (void)n_in; (void)out_size;

    initTab<<<3, 256>>>();
    ph1<<<dim3(NBH, 5, NPART), 256>>>(k, v);
    cvtM3<<<(NBH * 36 * 5 * 32) / 256, 256>>>();
    ph2<<<dim3(NBH, 16), 256>>>(q, out);
}